// round 3
// baseline (speedup 1.0000x reference)
#include <cuda_runtime.h>

#define N_NODES 100000
#define NPAD    100032          // padded to multiple of 64
#define N_EDGES 800000
#define D       256

// ---------------- scratch (device globals: no allocations allowed) ----------
__device__ __align__(16) float g_agg[(size_t)NPAD * D];   // 102.4 MB
__device__ float g_cnt[NPAD];
__device__ __align__(16) float g_h1[(size_t)NPAD * D];    // 102.4 MB
__device__ int   g_is64;

// ---------------- zero scratch ----------------------------------------------
__global__ void zero_kernel() {
    int i = blockIdx.x * blockDim.x + threadIdx.x;
    int stride = gridDim.x * blockDim.x;
    float4 z = make_float4(0.f, 0.f, 0.f, 0.f);
    float4* a4 = reinterpret_cast<float4*>(g_agg);
    const int n4 = NPAD * (D / 4);
    for (int j = i; j < n4; j += stride) a4[j] = z;
    for (int j = i; j < NPAD; j += stride) g_cnt[j] = 0.f;
}

// ---------------- int32 vs int64 edge_index detection -----------------------
// jnp.int64 without x64 enabled silently becomes int32. Values < 2^31, so if
// the buffer really is int64, every odd 32-bit word (high half) is zero.
__global__ void detect_kernel(const int* __restrict__ ei32) {
    if (blockIdx.x == 0 && threadIdx.x == 0) {
        int odd_or = 0;
        #pragma unroll 8
        for (int i = 0; i < 64; i++) odd_or |= ei32[2 * i + 1];
        g_is64 = (odd_or == 0) ? 1 : 0;
    }
}

// ---------------- scatter-add aggregation -----------------------------------
__device__ __forceinline__ void red_add_v4(float4* p, float4 v) {
    asm volatile("red.global.add.v4.f32 [%0], {%1, %2, %3, %4};"
                 :: "l"(p), "f"(v.x), "f"(v.y), "f"(v.z), "f"(v.w)
                 : "memory");
}

__global__ __launch_bounds__(256) void scatter_kernel(
        const float4* __restrict__ x4, const long long* __restrict__ ei64) {
    int t = blockIdx.x * blockDim.x + threadIdx.x;
    int e = t >> 6;        // 64 float4 chunks per 256-float row
    int c = t & 63;
    if (e >= N_EDGES) return;
    int src, dst;
    if (g_is64) {
        src = (int)ei64[e];
        dst = (int)ei64[N_EDGES + e];
    } else {
        const int* p = (const int*)ei64;
        src = p[e];
        dst = p[N_EDGES + e];
    }
    float4 v = x4[src * (D / 4) + c];
    float4* agg4 = reinterpret_cast<float4*>(g_agg);
    red_add_v4(&agg4[dst * (D / 4) + c], v);
    if (c == 0) atomicAdd(&g_cnt[dst], 1.0f);
}

// ---------------- SAGEConv GEMM: h1 = relu(mean@Wl^T + x@Wr^T + b) + x ------
#define BM 64
#define BN 64
#define BK 16
#define PADW 68

__global__ __launch_bounds__(256) void conv_kernel(
        const float* __restrict__ x,  const float* __restrict__ Wl,
        const float* __restrict__ bias_l, const float* __restrict__ Wr) {
    __shared__ float Am[BK][PADW], Ax[BK][PADW];
    __shared__ float Bl[BK][PADW], Br[BK][PADW];
    __shared__ float invc[BM];

    int t  = threadIdx.x;
    int m0 = blockIdx.y * BM;           // node tile
    int n0 = blockIdx.x * BN;           // out-channel tile

    if (t < BM) {
        float c = g_cnt[m0 + t];
        invc[t] = 1.0f / fmaxf(c, 1.0f);
    }
    __syncthreads();

    int lm = t >> 2;                    // load row 0..63
    int lk = (t & 3) * 4;               // load k offset 0/4/8/12
    int ty = t >> 4, tx = t & 15;

    float acc[4][4];
    #pragma unroll
    for (int i = 0; i < 4; i++)
        #pragma unroll
        for (int j = 0; j < 4; j++) acc[i][j] = 0.f;

    for (int k0 = 0; k0 < D; k0 += BK) {
        int gm = m0 + lm;
        float4 va = *(const float4*)&g_agg[(size_t)gm * D + k0 + lk];
        float4 vx = make_float4(0.f, 0.f, 0.f, 0.f);
        if (gm < N_NODES)
            vx = *(const float4*)&x[(size_t)gm * D + k0 + lk];
        float iv = invc[lm];
        Am[lk+0][lm] = va.x * iv; Am[lk+1][lm] = va.y * iv;
        Am[lk+2][lm] = va.z * iv; Am[lk+3][lm] = va.w * iv;
        Ax[lk+0][lm] = vx.x; Ax[lk+1][lm] = vx.y;
        Ax[lk+2][lm] = vx.z; Ax[lk+3][lm] = vx.w;

        int go = n0 + lm;
        float4 vl = *(const float4*)&Wl[go * D + k0 + lk];
        float4 vr = *(const float4*)&Wr[go * D + k0 + lk];
        Bl[lk+0][lm] = vl.x; Bl[lk+1][lm] = vl.y;
        Bl[lk+2][lm] = vl.z; Bl[lk+3][lm] = vl.w;
        Br[lk+0][lm] = vr.x; Br[lk+1][lm] = vr.y;
        Br[lk+2][lm] = vr.z; Br[lk+3][lm] = vr.w;
        __syncthreads();

        #pragma unroll
        for (int kk = 0; kk < BK; kk++) {
            float am[4], axv[4], blv[4], brv[4];
            *(float4*)am  = *(const float4*)&Am[kk][ty * 4];
            *(float4*)axv = *(const float4*)&Ax[kk][ty * 4];
            *(float4*)blv = *(const float4*)&Bl[kk][tx * 4];
            *(float4*)brv = *(const float4*)&Br[kk][tx * 4];
            #pragma unroll
            for (int i = 0; i < 4; i++)
                #pragma unroll
                for (int j = 0; j < 4; j++)
                    acc[i][j] += am[i] * blv[j] + axv[i] * brv[j];
        }
        __syncthreads();
    }

    #pragma unroll
    for (int i = 0; i < 4; i++) {
        int n = m0 + ty * 4 + i;
        if (n < N_NODES) {
            #pragma unroll
            for (int j = 0; j < 4; j++) {
                int o = n0 + tx * 4 + j;
                float v = acc[i][j] + bias_l[o];
                v = fmaxf(v, 0.f) + x[(size_t)n * D + o];   // relu + residual
                g_h1[(size_t)n * D + o] = v;
            }
        }
    }
}

// ---------------- fused MLP: 256->128->32->1 --------------------------------
struct MlpSmem {
    float W1s[128][260];   // untransposed, row-padded (260%32==4 -> conflict-free)
    float W2s[32][132];
    float h1s[32][260];
    float h2s[32][132];
    float h3s[32][36];
    float b1s[128];
    float b2s[32];
    float W3s[32];
    float b3s;
};

__global__ __launch_bounds__(256) void mlp_kernel(
        const float* __restrict__ W1, const float* __restrict__ b1,
        const float* __restrict__ W2, const float* __restrict__ b2,
        const float* __restrict__ W3, const float* __restrict__ b3,
        float* __restrict__ out) {
    extern __shared__ MlpSmem smem_buf[];
    MlpSmem* s = smem_buf;
    int t  = threadIdx.x;
    int n0 = blockIdx.x * 32;

    const float4* W14 = (const float4*)W1;
    for (int f = t; f < 128 * 64; f += 256) {
        int o = f >> 6, k4 = f & 63;
        *(float4*)&s->W1s[o][k4 * 4] = W14[f];
    }
    const float4* W24 = (const float4*)W2;
    for (int f = t; f < 32 * 32; f += 256) {
        int o = f >> 5, k4 = f & 31;
        *(float4*)&s->W2s[o][k4 * 4] = W24[f];
    }
    const float4* h14 = (const float4*)g_h1;
    for (int f = t; f < 32 * 64; f += 256) {
        int node = f >> 6, k4 = f & 63;
        *(float4*)&s->h1s[node][k4 * 4] = h14[(size_t)(n0 + node) * 64 + k4];
    }
    if (t < 128) s->b1s[t] = b1[t];
    if (t < 32) { s->b2s[t] = b2[t]; s->W3s[t] = W3[t]; }
    if (t == 0) s->b3s = b3[0];
    __syncthreads();

    int node = t >> 3;     // 32 nodes, 8 threads per node
    int og   = t & 7;      // outputs interleaved: o = og + 8*j (conflict-free LDS)

    // layer 1: 256 -> 128, 16 outputs/thread
    {
        float acc[16];
        #pragma unroll
        for (int j = 0; j < 16; j++) acc[j] = s->b1s[og + 8 * j];
        for (int k4 = 0; k4 < 64; k4++) {
            float4 h = *(const float4*)&s->h1s[node][k4 * 4];
            #pragma unroll
            for (int j = 0; j < 16; j++) {
                float4 w = *(const float4*)&s->W1s[og + 8 * j][k4 * 4];
                acc[j] += h.x * w.x + h.y * w.y + h.z * w.z + h.w * w.w;
            }
        }
        #pragma unroll
        for (int j = 0; j < 16; j++)
            s->h2s[node][og + 8 * j] = fmaxf(acc[j], 0.f);
    }
    __syncthreads();

    // layer 2: 128 -> 32, 4 outputs/thread
    {
        float acc[4];
        #pragma unroll
        for (int j = 0; j < 4; j++) acc[j] = s->b2s[og + 8 * j];
        for (int k4 = 0; k4 < 32; k4++) {
            float4 h = *(const float4*)&s->h2s[node][k4 * 4];
            #pragma unroll
            for (int j = 0; j < 4; j++) {
                float4 w = *(const float4*)&s->W2s[og + 8 * j][k4 * 4];
                acc[j] += h.x * w.x + h.y * w.y + h.z * w.z + h.w * w.w;
            }
        }
        #pragma unroll
        for (int j = 0; j < 4; j++)
            s->h3s[node][og + 8 * j] = fmaxf(acc[j], 0.f);
    }
    __syncthreads();

    // layer 3: 32 -> 1
    if (t < 32) {
        int n = n0 + t;
        if (n < N_NODES) {
            float v = s->b3s;
            #pragma unroll
            for (int k = 0; k < 32; k++) v += s->h3s[t][k] * s->W3s[k];
            out[n] = v;
        }
    }
}

// ---------------- launch -----------------------------------------------------
extern "C" void kernel_launch(void* const* d_in, const int* in_sizes, int n_in,
                              void* d_out, int out_size) {
    const float*     x  = (const float*)d_in[0];
    const long long* ei = (const long long*)d_in[1];
    const float*     Wl = (const float*)d_in[2];
    const float*     bl = (const float*)d_in[3];
    const float*     Wr = (const float*)d_in[4];
    const float*     W1 = (const float*)d_in[5];
    const float*     b1 = (const float*)d_in[6];
    const float*     W2 = (const float*)d_in[7];
    const float*     b2 = (const float*)d_in[8];
    const float*     W3 = (const float*)d_in[9];
    const float*     b3 = (const float*)d_in[10];
    float* out = (float*)d_out;

    zero_kernel<<<2048, 256>>>();
    detect_kernel<<<1, 32>>>((const int*)ei);
    scatter_kernel<<<(N_EDGES * 64) / 256, 256>>>((const float4*)x, ei);
    conv_kernel<<<dim3(D / BN, NPAD / BM), 256>>>(x, Wl, bl, Wr);

    cudaFuncSetAttribute(mlp_kernel, cudaFuncAttributeMaxDynamicSharedMemorySize,
                         (int)sizeof(MlpSmem));
    mlp_kernel<<<NPAD / 32, 256, sizeof(MlpSmem)>>>(W1, b1, W2, b2, W3, b3, out);
}

// round 4
// speedup vs baseline: 1.1762x; 1.1762x over previous
#include <cuda_runtime.h>

#define N_NODES 100000
#define NPAD    100096          // multiple of 128 (conv BM) and 32 (mlp)
#define N_EDGES 800000
#define D       256

// ---------------- scratch (device globals: no allocations allowed) ----------
__device__ __align__(16) float g_agg[(size_t)NPAD * D];   // ~102.5 MB
__device__ float g_cnt[NPAD];
__device__ __align__(16) float g_h1[(size_t)NPAD * D];    // ~102.5 MB
__device__ int   g_is64;

// ---------------- zero scratch ----------------------------------------------
__global__ void zero_kernel() {
    int i = blockIdx.x * blockDim.x + threadIdx.x;
    int stride = gridDim.x * blockDim.x;
    float4 z = make_float4(0.f, 0.f, 0.f, 0.f);
    float4* a4 = reinterpret_cast<float4*>(g_agg);
    const int n4 = NPAD * (D / 4);
    for (int j = i; j < n4; j += stride) a4[j] = z;
    for (int j = i; j < NPAD; j += stride) g_cnt[j] = 0.f;
}

// ---------------- int32 vs int64 edge_index detection -----------------------
__global__ void detect_kernel(const int* __restrict__ ei32) {
    if (blockIdx.x == 0 && threadIdx.x == 0) {
        int odd_or = 0;
        #pragma unroll 8
        for (int i = 0; i < 64; i++) odd_or |= ei32[2 * i + 1];
        g_is64 = (odd_or == 0) ? 1 : 0;
    }
}

// ---------------- scatter-add aggregation -----------------------------------
__device__ __forceinline__ void red_add_v4(float4* p, float4 v) {
    asm volatile("red.global.add.v4.f32 [%0], {%1, %2, %3, %4};"
                 :: "l"(p), "f"(v.x), "f"(v.y), "f"(v.z), "f"(v.w)
                 : "memory");
}

__global__ __launch_bounds__(256) void scatter_kernel(
        const float4* __restrict__ x4, const long long* __restrict__ ei64) {
    int t = blockIdx.x * blockDim.x + threadIdx.x;
    int e = t >> 6;        // 64 float4 chunks per 256-float row
    int c = t & 63;
    if (e >= N_EDGES) return;
    int src, dst;
    if (g_is64) {
        src = (int)ei64[e];
        dst = (int)ei64[N_EDGES + e];
    } else {
        const int* p = (const int*)ei64;
        src = p[e];
        dst = p[N_EDGES + e];
    }
    float4 v = x4[src * (D / 4) + c];
    float4* agg4 = reinterpret_cast<float4*>(g_agg);
    red_add_v4(&agg4[dst * (D / 4) + c], v);
    if (c == 0) atomicAdd(&g_cnt[dst], 1.0f);
}

// ---------------- packed f32x2 helpers ---------------------------------------
typedef unsigned long long u64;

__device__ __forceinline__ u64 f32x2_fma(u64 a, u64 b, u64 c) {
    u64 d;
    asm("fma.rn.f32x2 %0, %1, %2, %3;" : "=l"(d) : "l"(a), "l"(b), "l"(c));
    return d;
}
__device__ __forceinline__ u64 dup2(float v) {
    u64 d;
    asm("mov.b64 %0, {%1, %1};" : "=l"(d) : "f"(v));
    return d;
}

// ---------------- SAGEConv GEMM: h1 = relu(mean@Wl^T + x@Wr^T + b) + x ------
// BM=128 x BN=64 tile, 256 threads, per-thread 8x4 via packed f32x2 FMA.
#define BM 128
#define BN 64
#define BK 16
#define BMP 132
#define BNP 68

__global__ __launch_bounds__(256, 2) void conv_kernel(
        const float* __restrict__ x,  const float* __restrict__ Wl,
        const float* __restrict__ bias_l, const float* __restrict__ Wr) {
    __shared__ float Am[BK][BMP], Ax[BK][BMP];
    __shared__ float Bl[BK][BNP], Br[BK][BNP];
    __shared__ float invc[BM];

    int t  = threadIdx.x;
    int m0 = blockIdx.y * BM;           // node tile
    int n0 = blockIdx.x * BN;           // out-channel tile

    if (t < BM) {
        float c = g_cnt[m0 + t];
        invc[t] = 1.0f / fmaxf(c, 1.0f);
    }
    __syncthreads();

    int ty = t >> 4;                    // 0..15 -> M sub-tile of 8 rows
    int tx = t & 15;                    // 0..15 -> N sub-tile of 4 cols
    int lmB = t >> 2;                   // B-tile loader row 0..63
    int lkB = (t & 3) * 4;              // B-tile loader k offset

    u64 acc[4][4];                      // [m-pair][n] packed f32x2 accumulators
    #pragma unroll
    for (int i = 0; i < 4; i++)
        #pragma unroll
        for (int j = 0; j < 4; j++) acc[i][j] = 0ull;

    for (int k0 = 0; k0 < D; k0 += BK) {
        // --- load A tiles (g_agg scaled by 1/cnt, and x) : 128 x 16 each ----
        #pragma unroll
        for (int rep = 0; rep < 2; rep++) {
            int idx = t + rep * 256;
            int lm = idx >> 2;
            int lk = (idx & 3) * 4;
            int gm = m0 + lm;
            float4 va = *(const float4*)&g_agg[(size_t)gm * D + k0 + lk];
            float4 vx = make_float4(0.f, 0.f, 0.f, 0.f);
            if (gm < N_NODES)
                vx = *(const float4*)&x[(size_t)gm * D + k0 + lk];
            float iv = invc[lm];
            Am[lk+0][lm] = va.x * iv; Am[lk+1][lm] = va.y * iv;
            Am[lk+2][lm] = va.z * iv; Am[lk+3][lm] = va.w * iv;
            Ax[lk+0][lm] = vx.x; Ax[lk+1][lm] = vx.y;
            Ax[lk+2][lm] = vx.z; Ax[lk+3][lm] = vx.w;
        }
        // --- load B tiles (Wl, Wr) : 64 x 16 each ---------------------------
        {
            int go = n0 + lmB;
            float4 vl = *(const float4*)&Wl[go * D + k0 + lkB];
            float4 vr = *(const float4*)&Wr[go * D + k0 + lkB];
            Bl[lkB+0][lmB] = vl.x; Bl[lkB+1][lmB] = vl.y;
            Bl[lkB+2][lmB] = vl.z; Bl[lkB+3][lmB] = vl.w;
            Br[lkB+0][lmB] = vr.x; Br[lkB+1][lmB] = vr.y;
            Br[lkB+2][lmB] = vr.z; Br[lkB+3][lmB] = vr.w;
        }
        __syncthreads();

        #pragma unroll
        for (int kk = 0; kk < BK; kk++) {
            // A operand pairs come straight out of LDS.128 as 64-bit pairs
            const ulonglong2* amp = (const ulonglong2*)&Am[kk][ty * 8];
            const ulonglong2* axp = (const ulonglong2*)&Ax[kk][ty * 8];
            ulonglong2 am01 = amp[0], am23 = amp[1];
            ulonglong2 ax01 = axp[0], ax23 = axp[1];
            u64 ap[4] = { am01.x, am01.y, am23.x, am23.y };
            u64 xp[4] = { ax01.x, ax01.y, ax23.x, ax23.y };

            float4 bl = *(const float4*)&Bl[kk][tx * 4];
            float4 br = *(const float4*)&Br[kk][tx * 4];
            u64 bl2[4] = { dup2(bl.x), dup2(bl.y), dup2(bl.z), dup2(bl.w) };
            u64 br2[4] = { dup2(br.x), dup2(br.y), dup2(br.z), dup2(br.w) };

            #pragma unroll
            for (int i = 0; i < 4; i++)
                #pragma unroll
                for (int j = 0; j < 4; j++) {
                    acc[i][j] = f32x2_fma(ap[i], bl2[j], acc[i][j]);
                    acc[i][j] = f32x2_fma(xp[i], br2[j], acc[i][j]);
                }
        }
        __syncthreads();
    }

    // --- epilogue: bias, relu, residual, store ------------------------------
    float4 bf = *(const float4*)&bias_l[n0 + tx * 4];
    #pragma unroll
    for (int i2 = 0; i2 < 4; i2++) {
        float2 a0 = *(float2*)&acc[i2][0];
        float2 a1 = *(float2*)&acc[i2][1];
        float2 a2 = *(float2*)&acc[i2][2];
        float2 a3 = *(float2*)&acc[i2][3];
        #pragma unroll
        for (int h = 0; h < 2; h++) {
            int n = m0 + ty * 8 + i2 * 2 + h;
            if (n < N_NODES) {
                float4 xr = *(const float4*)&x[(size_t)n * D + n0 + tx * 4];
                float4 r;
                r.x = fmaxf((h ? a0.y : a0.x) + bf.x, 0.f) + xr.x;
                r.y = fmaxf((h ? a1.y : a1.x) + bf.y, 0.f) + xr.y;
                r.z = fmaxf((h ? a2.y : a2.x) + bf.z, 0.f) + xr.z;
                r.w = fmaxf((h ? a3.y : a3.x) + bf.w, 0.f) + xr.w;
                *(float4*)&g_h1[(size_t)n * D + n0 + tx * 4] = r;
            }
        }
    }
}

// ---------------- fused MLP: 256->128->32->1 --------------------------------
struct MlpSmem {
    float W1s[128][260];
    float W2s[32][132];
    float h1s[32][260];
    float h2s[32][132];
    float h3s[32][36];
    float b1s[128];
    float b2s[32];
    float W3s[32];
    float b3s;
};

__global__ __launch_bounds__(256) void mlp_kernel(
        const float* __restrict__ W1, const float* __restrict__ b1,
        const float* __restrict__ W2, const float* __restrict__ b2,
        const float* __restrict__ W3, const float* __restrict__ b3,
        float* __restrict__ out) {
    extern __shared__ MlpSmem smem_buf[];
    MlpSmem* s = smem_buf;
    int t  = threadIdx.x;
    int n0 = blockIdx.x * 32;

    const float4* W14 = (const float4*)W1;
    for (int f = t; f < 128 * 64; f += 256) {
        int o = f >> 6, k4 = f & 63;
        *(float4*)&s->W1s[o][k4 * 4] = W14[f];
    }
    const float4* W24 = (const float4*)W2;
    for (int f = t; f < 32 * 32; f += 256) {
        int o = f >> 5, k4 = f & 31;
        *(float4*)&s->W2s[o][k4 * 4] = W24[f];
    }
    const float4* h14 = (const float4*)g_h1;
    for (int f = t; f < 32 * 64; f += 256) {
        int node = f >> 6, k4 = f & 63;
        *(float4*)&s->h1s[node][k4 * 4] = h14[(size_t)(n0 + node) * 64 + k4];
    }
    if (t < 128) s->b1s[t] = b1[t];
    if (t < 32) { s->b2s[t] = b2[t]; s->W3s[t] = W3[t]; }
    if (t == 0) s->b3s = b3[0];
    __syncthreads();

    int node = t >> 3;
    int og   = t & 7;

    // layer 1: 256 -> 128, 16 outputs/thread
    {
        float acc[16];
        #pragma unroll
        for (int j = 0; j < 16; j++) acc[j] = s->b1s[og + 8 * j];
        for (int k4 = 0; k4 < 64; k4++) {
            float4 h = *(const float4*)&s->h1s[node][k4 * 4];
            #pragma unroll
            for (int j = 0; j < 16; j++) {
                float4 w = *(const float4*)&s->W1s[og + 8 * j][k4 * 4];
                acc[j] += h.x * w.x + h.y * w.y + h.z * w.z + h.w * w.w;
            }
        }
        #pragma unroll
        for (int j = 0; j < 16; j++)
            s->h2s[node][og + 8 * j] = fmaxf(acc[j], 0.f);
    }
    __syncthreads();

    // layer 2: 128 -> 32, 4 outputs/thread
    {
        float acc[4];
        #pragma unroll
        for (int j = 0; j < 4; j++) acc[j] = s->b2s[og + 8 * j];
        for (int k4 = 0; k4 < 32; k4++) {
            float4 h = *(const float4*)&s->h2s[node][k4 * 4];
            #pragma unroll
            for (int j = 0; j < 4; j++) {
                float4 w = *(const float4*)&s->W2s[og + 8 * j][k4 * 4];
                acc[j] += h.x * w.x + h.y * w.y + h.z * w.z + h.w * w.w;
            }
        }
        #pragma unroll
        for (int j = 0; j < 4; j++)
            s->h3s[node][og + 8 * j] = fmaxf(acc[j], 0.f);
    }
    __syncthreads();

    // layer 3: 32 -> 1
    if (t < 32) {
        int n = n0 + t;
        if (n < N_NODES) {
            float v = s->b3s;
            #pragma unroll
            for (int k = 0; k < 32; k++) v += s->h3s[t][k] * s->W3s[k];
            out[n] = v;
        }
    }
}

// ---------------- launch -----------------------------------------------------
extern "C" void kernel_launch(void* const* d_in, const int* in_sizes, int n_in,
                              void* d_out, int out_size) {
    const float*     x  = (const float*)d_in[0];
    const long long* ei = (const long long*)d_in[1];
    const float*     Wl = (const float*)d_in[2];
    const float*     bl = (const float*)d_in[3];
    const float*     Wr = (const float*)d_in[4];
    const float*     W1 = (const float*)d_in[5];
    const float*     b1 = (const float*)d_in[6];
    const float*     W2 = (const float*)d_in[7];
    const float*     b2 = (const float*)d_in[8];
    const float*     W3 = (const float*)d_in[9];
    const float*     b3 = (const float*)d_in[10];
    float* out = (float*)d_out;

    zero_kernel<<<2048, 256>>>();
    detect_kernel<<<1, 32>>>((const int*)ei);
    scatter_kernel<<<(N_EDGES * 64) / 256, 256>>>((const float4*)x, ei);
    conv_kernel<<<dim3(D / BN, NPAD / BM), 256>>>(x, Wl, bl, Wr);

    cudaFuncSetAttribute(mlp_kernel, cudaFuncAttributeMaxDynamicSharedMemorySize,
                         (int)sizeof(MlpSmem));
    mlp_kernel<<<NPAD / 32, 256, sizeof(MlpSmem)>>>(W1, b1, W2, b2, W3, b3, out);
}

// round 5
// speedup vs baseline: 1.2435x; 1.0572x over previous
#include <cuda_runtime.h>

#define N_NODES 100000
#define NPAD    100096          // multiple of 128 (conv BM) and 32 (mlp)
#define N_EDGES 800000
#define D       256

// ---------------- scratch (device globals: no allocations allowed) ----------
__device__ __align__(16) float g_agg[(size_t)NPAD * D];   // ~102.5 MB
__device__ float g_cnt[NPAD];
__device__ __align__(16) float g_h1[(size_t)NPAD * D];    // ~102.5 MB
__device__ int   g_is64;

// ---------------- zero scratch ----------------------------------------------
__global__ void zero_kernel() {
    int i = blockIdx.x * blockDim.x + threadIdx.x;
    int stride = gridDim.x * blockDim.x;
    float4 z = make_float4(0.f, 0.f, 0.f, 0.f);
    float4* a4 = reinterpret_cast<float4*>(g_agg);
    const int n4 = NPAD * (D / 4);
    for (int j = i; j < n4; j += stride) a4[j] = z;
    for (int j = i; j < NPAD; j += stride) g_cnt[j] = 0.f;
}

// ---------------- int32 vs int64 edge_index detection -----------------------
__global__ void detect_kernel(const int* __restrict__ ei32) {
    if (blockIdx.x == 0 && threadIdx.x == 0) {
        int odd_or = 0;
        #pragma unroll 8
        for (int i = 0; i < 64; i++) odd_or |= ei32[2 * i + 1];
        g_is64 = (odd_or == 0) ? 1 : 0;
    }
}

// ---------------- scatter-add aggregation -----------------------------------
// 8 threads per edge, 8 float4 chunks per thread (front-batched loads).
__device__ __forceinline__ void red_add_v4(float4* p, float4 v) {
    asm volatile("red.global.add.v4.f32 [%0], {%1, %2, %3, %4};"
                 :: "l"(p), "f"(v.x), "f"(v.y), "f"(v.z), "f"(v.w)
                 : "memory");
}

__global__ __launch_bounds__(256) void scatter_kernel(
        const float4* __restrict__ x4, const long long* __restrict__ ei64) {
    int t = blockIdx.x * blockDim.x + threadIdx.x;
    int e  = t >> 3;
    int c0 = t & 7;
    if (e >= N_EDGES) return;
    int src, dst;
    if (g_is64) {
        src = (int)ei64[e];
        dst = (int)ei64[N_EDGES + e];
    } else {
        const int* p = (const int*)ei64;
        src = p[e];
        dst = p[N_EDGES + e];
    }
    const float4* xr = x4 + (size_t)src * (D / 4);
    float4*       ar = reinterpret_cast<float4*>(g_agg) + (size_t)dst * (D / 4);
    float4 v[8];
    #pragma unroll
    for (int i = 0; i < 8; i++) v[i] = __ldg(&xr[c0 + 8 * i]);
    #pragma unroll
    for (int i = 0; i < 8; i++) red_add_v4(&ar[c0 + 8 * i], v[i]);
    if (c0 == 0) atomicAdd(&g_cnt[dst], 1.0f);
}

// ---------------- packed f32x2 helpers ---------------------------------------
typedef unsigned long long u64;

__device__ __forceinline__ u64 f32x2_fma(u64 a, u64 b, u64 c) {
    u64 d;
    asm("fma.rn.f32x2 %0, %1, %2, %3;" : "=l"(d) : "l"(a), "l"(b), "l"(c));
    return d;
}
__device__ __forceinline__ u64 dup2(float v) {
    u64 d;
    asm("mov.b64 %0, {%1, %1};" : "=l"(d) : "f"(v));
    return d;
}

// ---------------- SAGEConv GEMM: h1 = relu(mean@Wl^T + x@Wr^T + b) + x ------
// BM=128 x BN=64, 256 threads, 8x4 per thread via f32x2, double-buffered smem.
#define BM 128
#define BN 64
#define BK 16
#define BMP 132
#define BNP 68
#define NKT (D / BK)

__global__ __launch_bounds__(256, 2) void conv_kernel(
        const float* __restrict__ x,  const float* __restrict__ Wl,
        const float* __restrict__ bias_l, const float* __restrict__ Wr) {
    __shared__ float Am[2][BK][BMP], Ax[2][BK][BMP];
    __shared__ float Bl[2][BK][BNP], Br[2][BK][BNP];
    __shared__ float invc[BM];

    int t  = threadIdx.x;
    int m0 = blockIdx.y * BM;           // node tile
    int n0 = blockIdx.x * BN;           // out-channel tile

    if (t < BM) {
        float c = g_cnt[m0 + t];
        invc[t] = 1.0f / fmaxf(c, 1.0f);
    }

    int lm0 = t >> 2;                   // A loader rows (rep0: 0..63)
    int lm1 = lm0 + 64;                 // rep1: 64..127
    int lk  = (t & 3) * 4;              // k offset 0/4/8/12
    int ty  = t >> 4;                   // 0..15 -> 8 M rows
    int tx  = t & 15;                   // 0..15 -> 4 N cols

    u64 acc[4][4];
    #pragma unroll
    for (int i = 0; i < 4; i++)
        #pragma unroll
        for (int j = 0; j < 4; j++) acc[i][j] = 0ull;

    float4 pva0, pvx0, pva1, pvx1, pvl, pvr;

    // ---- global-load of one K-tile into registers --------------------------
    #define LOAD_TILE(K0)                                                      \
    {   int gm0 = m0 + lm0, gm1 = m0 + lm1;                                    \
        pva0 = *(const float4*)&g_agg[(size_t)gm0 * D + (K0) + lk];            \
        pva1 = *(const float4*)&g_agg[(size_t)gm1 * D + (K0) + lk];            \
        pvx0 = make_float4(0.f, 0.f, 0.f, 0.f);                                \
        pvx1 = make_float4(0.f, 0.f, 0.f, 0.f);                                \
        if (gm0 < N_NODES) pvx0 = *(const float4*)&x[(size_t)gm0 * D + (K0) + lk]; \
        if (gm1 < N_NODES) pvx1 = *(const float4*)&x[(size_t)gm1 * D + (K0) + lk]; \
        pvl = *(const float4*)&Wl[(n0 + lm0) * D + (K0) + lk];                 \
        pvr = *(const float4*)&Wr[(n0 + lm0) * D + (K0) + lk];                 \
    }

    // ---- register tile -> smem buffer --------------------------------------
    #define STORE_TILE(B)                                                      \
    {   float iv0 = invc[lm0], iv1 = invc[lm1];                                \
        Am[B][lk+0][lm0] = pva0.x * iv0; Am[B][lk+1][lm0] = pva0.y * iv0;      \
        Am[B][lk+2][lm0] = pva0.z * iv0; Am[B][lk+3][lm0] = pva0.w * iv0;      \
        Am[B][lk+0][lm1] = pva1.x * iv1; Am[B][lk+1][lm1] = pva1.y * iv1;      \
        Am[B][lk+2][lm1] = pva1.z * iv1; Am[B][lk+3][lm1] = pva1.w * iv1;      \
        Ax[B][lk+0][lm0] = pvx0.x; Ax[B][lk+1][lm0] = pvx0.y;                  \
        Ax[B][lk+2][lm0] = pvx0.z; Ax[B][lk+3][lm0] = pvx0.w;                  \
        Ax[B][lk+0][lm1] = pvx1.x; Ax[B][lk+1][lm1] = pvx1.y;                  \
        Ax[B][lk+2][lm1] = pvx1.z; Ax[B][lk+3][lm1] = pvx1.w;                  \
        Bl[B][lk+0][lm0] = pvl.x; Bl[B][lk+1][lm0] = pvl.y;                    \
        Bl[B][lk+2][lm0] = pvl.z; Bl[B][lk+3][lm0] = pvl.w;                    \
        Br[B][lk+0][lm0] = pvr.x; Br[B][lk+1][lm0] = pvr.y;                    \
        Br[B][lk+2][lm0] = pvr.z; Br[B][lk+3][lm0] = pvr.w;                    \
    }

    LOAD_TILE(0);
    __syncthreads();                    // invc ready
    STORE_TILE(0);
    __syncthreads();

    #pragma unroll 2
    for (int kt = 0; kt < NKT; kt++) {
        int cur = kt & 1;
        if (kt + 1 < NKT) LOAD_TILE((kt + 1) * BK);   // overlap with compute

        #pragma unroll
        for (int kk = 0; kk < BK; kk++) {
            const ulonglong2* amp = (const ulonglong2*)&Am[cur][kk][ty * 8];
            const ulonglong2* axp = (const ulonglong2*)&Ax[cur][kk][ty * 8];
            ulonglong2 am01 = amp[0], am23 = amp[1];
            ulonglong2 ax01 = axp[0], ax23 = axp[1];
            u64 ap[4] = { am01.x, am01.y, am23.x, am23.y };
            u64 xp[4] = { ax01.x, ax01.y, ax23.x, ax23.y };

            float4 bl = *(const float4*)&Bl[cur][kk][tx * 4];
            float4 br = *(const float4*)&Br[cur][kk][tx * 4];
            u64 bl2[4] = { dup2(bl.x), dup2(bl.y), dup2(bl.z), dup2(bl.w) };
            u64 br2[4] = { dup2(br.x), dup2(br.y), dup2(br.z), dup2(br.w) };

            #pragma unroll
            for (int i = 0; i < 4; i++)
                #pragma unroll
                for (int j = 0; j < 4; j++) {
                    acc[i][j] = f32x2_fma(ap[i], bl2[j], acc[i][j]);
                    acc[i][j] = f32x2_fma(xp[i], br2[j], acc[i][j]);
                }
        }
        if (kt + 1 < NKT) {
            STORE_TILE(cur ^ 1);
            __syncthreads();
        }
    }

    // --- epilogue: bias, relu, residual, store ------------------------------
    float4 bf = *(const float4*)&bias_l[n0 + tx * 4];
    #pragma unroll
    for (int i2 = 0; i2 < 4; i2++) {
        float2 a0 = *(float2*)&acc[i2][0];
        float2 a1 = *(float2*)&acc[i2][1];
        float2 a2 = *(float2*)&acc[i2][2];
        float2 a3 = *(float2*)&acc[i2][3];
        #pragma unroll
        for (int h = 0; h < 2; h++) {
            int n = m0 + ty * 8 + i2 * 2 + h;
            if (n < N_NODES) {
                float4 xr = *(const float4*)&x[(size_t)n * D + n0 + tx * 4];
                float4 r;
                r.x = fmaxf((h ? a0.y : a0.x) + bf.x, 0.f) + xr.x;
                r.y = fmaxf((h ? a1.y : a1.x) + bf.y, 0.f) + xr.y;
                r.z = fmaxf((h ? a2.y : a2.x) + bf.z, 0.f) + xr.z;
                r.w = fmaxf((h ? a3.y : a3.x) + bf.w, 0.f) + xr.w;
                *(float4*)&g_h1[(size_t)n * D + n0 + tx * 4] = r;
            }
        }
    }
}

// ---------------- fused MLP: 256->128->32->1 (f32x2 along K) ----------------
struct MlpSmem {
    float W1s[128][260];
    float W2s[32][132];
    float h1s[32][260];
    float h2s[32][132];
    float h3s[32][36];
    float b1s[128];
    float b2s[32];
    float W3s[32];
    float b3s;
};

__global__ __launch_bounds__(256) void mlp_kernel(
        const float* __restrict__ W1, const float* __restrict__ b1,
        const float* __restrict__ W2, const float* __restrict__ b2,
        const float* __restrict__ W3, const float* __restrict__ b3,
        float* __restrict__ out) {
    extern __shared__ MlpSmem smem_buf[];
    MlpSmem* s = smem_buf;
    int t  = threadIdx.x;
    int n0 = blockIdx.x * 32;

    const float4* W14 = (const float4*)W1;
    for (int f = t; f < 128 * 64; f += 256) {
        int o = f >> 6, k4 = f & 63;
        *(float4*)&s->W1s[o][k4 * 4] = W14[f];
    }
    const float4* W24 = (const float4*)W2;
    for (int f = t; f < 32 * 32; f += 256) {
        int o = f >> 5, k4 = f & 31;
        *(float4*)&s->W2s[o][k4 * 4] = W24[f];
    }
    const float4* h14 = (const float4*)g_h1;
    for (int f = t; f < 32 * 64; f += 256) {
        int node = f >> 6, k4 = f & 63;
        *(float4*)&s->h1s[node][k4 * 4] = h14[(size_t)(n0 + node) * 64 + k4];
    }
    if (t < 128) s->b1s[t] = b1[t];
    if (t < 32) { s->b2s[t] = b2[t]; s->W3s[t] = W3[t]; }
    if (t == 0) s->b3s = b3[0];
    __syncthreads();

    int node = t >> 3;
    int og   = t & 7;

    // layer 1: 256 -> 128, 16 outputs/thread, packed pairs along K
    {
        u64 acc[16];
        #pragma unroll
        for (int j = 0; j < 16; j++) acc[j] = 0ull;
        for (int k4 = 0; k4 < 64; k4++) {
            ulonglong2 h = *(const ulonglong2*)&s->h1s[node][k4 * 4];
            #pragma unroll
            for (int j = 0; j < 16; j++) {
                ulonglong2 w = *(const ulonglong2*)&s->W1s[og + 8 * j][k4 * 4];
                acc[j] = f32x2_fma(h.x, w.x, acc[j]);
                acc[j] = f32x2_fma(h.y, w.y, acc[j]);
            }
        }
        #pragma unroll
        for (int j = 0; j < 16; j++) {
            float2 a = *(float2*)&acc[j];
            s->h2s[node][og + 8 * j] = fmaxf(a.x + a.y + s->b1s[og + 8 * j], 0.f);
        }
    }
    __syncthreads();

    // layer 2: 128 -> 32, 4 outputs/thread
    {
        u64 acc[4];
        #pragma unroll
        for (int j = 0; j < 4; j++) acc[j] = 0ull;
        for (int k4 = 0; k4 < 32; k4++) {
            ulonglong2 h = *(const ulonglong2*)&s->h2s[node][k4 * 4];
            #pragma unroll
            for (int j = 0; j < 4; j++) {
                ulonglong2 w = *(const ulonglong2*)&s->W2s[og + 8 * j][k4 * 4];
                acc[j] = f32x2_fma(h.x, w.x, acc[j]);
                acc[j] = f32x2_fma(h.y, w.y, acc[j]);
            }
        }
        #pragma unroll
        for (int j = 0; j < 4; j++) {
            float2 a = *(float2*)&acc[j];
            s->h3s[node][og + 8 * j] = fmaxf(a.x + a.y + s->b2s[og + 8 * j], 0.f);
        }
    }
    __syncthreads();

    // layer 3: 32 -> 1
    if (t < 32) {
        int n = n0 + t;
        if (n < N_NODES) {
            float v = s->b3s;
            #pragma unroll
            for (int k = 0; k < 32; k++) v += s->h3s[t][k] * s->W3s[k];
            out[n] = v;
        }
    }
}

// ---------------- launch -----------------------------------------------------
extern "C" void kernel_launch(void* const* d_in, const int* in_sizes, int n_in,
                              void* d_out, int out_size) {
    const float*     x  = (const float*)d_in[0];
    const long long* ei = (const long long*)d_in[1];
    const float*     Wl = (const float*)d_in[2];
    const float*     bl = (const float*)d_in[3];
    const float*     Wr = (const float*)d_in[4];
    const float*     W1 = (const float*)d_in[5];
    const float*     b1 = (const float*)d_in[6];
    const float*     W2 = (const float*)d_in[7];
    const float*     b2 = (const float*)d_in[8];
    const float*     W3 = (const float*)d_in[9];
    const float*     b3 = (const float*)d_in[10];
    float* out = (float*)d_out;

    zero_kernel<<<2048, 256>>>();
    detect_kernel<<<1, 32>>>((const int*)ei);
    scatter_kernel<<<(N_EDGES * 8 + 255) / 256, 256>>>((const float4*)x, ei);
    conv_kernel<<<dim3(D / BN, NPAD / BM), 256>>>(x, Wl, bl, Wr);

    cudaFuncSetAttribute(mlp_kernel, cudaFuncAttributeMaxDynamicSharedMemorySize,
                         (int)sizeof(MlpSmem));
    mlp_kernel<<<NPAD / 32, 256, sizeof(MlpSmem)>>>(W1, b1, W2, b2, W3, b3, out);
}

// round 9
// speedup vs baseline: 1.5260x; 1.2272x over previous
#include <cuda_runtime.h>
#include <cuda_bf16.h>
#include <cstdint>

#define N_NODES 100000
#define NPAD    100096          // multiple of 128 (conv tile) and 32 (mlp)
#define N_EDGES 800000
#define D       256
#define KDIM    512             // GEMM K = 2*D  ([mean | x])

// ---------------- scratch (device globals: no allocations allowed) ----------
__device__ __align__(16) float g_agg[(size_t)NPAD * D];   // ~102.5 MB
__device__ float g_cnt[NPAD];
__device__ __align__(16) float g_h1[(size_t)NPAD * D];    // ~102.5 MB
__device__ int   g_is64;
__device__ __align__(16) __nv_bfloat16 g_Bhi[256 * KDIM]; // 256 KB
__device__ __align__(16) __nv_bfloat16 g_Blo[256 * KDIM]; // 256 KB

// ---------------- zero scratch ----------------------------------------------
__global__ void zero_kernel() {
    int i = blockIdx.x * blockDim.x + threadIdx.x;
    int stride = gridDim.x * blockDim.x;
    float4 z = make_float4(0.f, 0.f, 0.f, 0.f);
    float4* a4 = reinterpret_cast<float4*>(g_agg);
    const int n4 = NPAD * (D / 4);
    for (int j = i; j < n4; j += stride) a4[j] = z;
    for (int j = i; j < NPAD; j += stride) g_cnt[j] = 0.f;
}

// ---------------- int32 vs int64 edge_index detection -----------------------
__global__ void detect_kernel(const int* __restrict__ ei32) {
    if (blockIdx.x == 0 && threadIdx.x == 0) {
        int odd_or = 0;
        #pragma unroll 8
        for (int i = 0; i < 64; i++) odd_or |= ei32[2 * i + 1];
        g_is64 = (odd_or == 0) ? 1 : 0;
    }
}

// ---------------- B prep: split [Wl | Wr] into bf16 hi/lo --------------------
__global__ void prep_kernel(const float* __restrict__ Wl, const float* __restrict__ Wr) {
    int idx = blockIdx.x * 256 + threadIdx.x;      // 256*512 = 131072 total
    int o = idx >> 9, k = idx & 511;
    float w = (k < 256) ? Wl[o * 256 + k] : Wr[o * 256 + (k - 256)];
    __nv_bfloat16 hi = __float2bfloat16(w);
    __nv_bfloat16 lo = __float2bfloat16(w - __bfloat162float(hi));
    g_Bhi[idx] = hi;
    g_Blo[idx] = lo;
}

// ---------------- scatter-add aggregation -----------------------------------
__device__ __forceinline__ void red_add_v4(float4* p, float4 v) {
    asm volatile("red.global.add.v4.f32 [%0], {%1, %2, %3, %4};"
                 :: "l"(p), "f"(v.x), "f"(v.y), "f"(v.z), "f"(v.w)
                 : "memory");
}

__global__ __launch_bounds__(256) void scatter_kernel(
        const float4* __restrict__ x4, const long long* __restrict__ ei64) {
    int t = blockIdx.x * blockDim.x + threadIdx.x;
    int e  = t >> 3;
    int c0 = t & 7;
    if (e >= N_EDGES) return;
    int src, dst;
    if (g_is64) {
        src = (int)ei64[e];
        dst = (int)ei64[N_EDGES + e];
    } else {
        const int* p = (const int*)ei64;
        src = p[e];
        dst = p[N_EDGES + e];
    }
    const float4* xr = x4 + (size_t)src * (D / 4);
    float4*       ar = reinterpret_cast<float4*>(g_agg) + (size_t)dst * (D / 4);
    float4 v[8];
    #pragma unroll
    for (int i = 0; i < 8; i++) v[i] = __ldg(&xr[c0 + 8 * i]);
    #pragma unroll
    for (int i = 0; i < 8; i++) red_add_v4(&ar[c0 + 8 * i], v[i]);
    if (c0 == 0) atomicAdd(&g_cnt[dst], 1.0f);
}

// ---------------- mma.sync helpers -------------------------------------------
__device__ __forceinline__ uint32_t smem_u32(const void* p) {
    uint32_t a;
    asm("{ .reg .u64 t; cvta.to.shared.u64 t, %1; cvt.u32.u64 %0, t; }"
        : "=r"(a) : "l"(p));
    return a;
}
__device__ __forceinline__ void ldsm_x4(uint32_t* r, uint32_t addr) {
    asm volatile("ldmatrix.sync.aligned.m8n8.x4.shared.b16 {%0,%1,%2,%3}, [%4];"
                 : "=r"(r[0]), "=r"(r[1]), "=r"(r[2]), "=r"(r[3]) : "r"(addr));
}
__device__ __forceinline__ void mma_bf16(float* d, const uint32_t* a,
                                         const uint32_t* b) {
    asm volatile("mma.sync.aligned.m16n8k16.row.col.f32.bf16.bf16.f32 "
                 "{%0,%1,%2,%3}, {%4,%5,%6,%7}, {%8,%9}, {%0,%1,%2,%3};"
                 : "+f"(d[0]), "+f"(d[1]), "+f"(d[2]), "+f"(d[3])
                 : "r"(a[0]), "r"(a[1]), "r"(a[2]), "r"(a[3]),
                   "r"(b[0]), "r"(b[1]));
}
__device__ __forceinline__ void cp_async16(uint32_t dst, const void* src) {
    asm volatile("cp.async.cg.shared.global [%0], [%1], 16;"
                 :: "r"(dst), "l"(src) : "memory");
}
#define CP_COMMIT() asm volatile("cp.async.commit_group;" ::: "memory")
#define CP_WAIT0()  asm volatile("cp.async.wait_group 0;" ::: "memory")

// ---------------- SAGEConv via mma.sync bf16-split ---------------------------
// C[128 x 128] = A[128 x 512] * B[128 x 512]^T per CTA (2 N-halves)
// A = [mean | x] (fp32 -> hi/lo bf16 in-flight),  B = [Wl | Wr] pre-split.
// 3 terms: Ahi*Bhi + Ahi*Blo + Alo*Bhi.
#define CH       64
#define NCH      (KDIM / CH)    // 8
#define RSTRIDE  144            // bytes per smem row (72 bf16, conflict-free)
#define SA_HI    0
#define SA_LO    18432
#define SB_HI    36864
#define SB_LO    55296
#define BUF      73728
#define SM_META  (2 * BUF)      // invc[128] then bias[128]
#define CONV_SMEM (SM_META + 1024)

__global__ __launch_bounds__(256) void conv_kernel(
        const float* __restrict__ x, const float* __restrict__ bias_l) {
    extern __shared__ char smem[];
    uint32_t sb = smem_u32(smem);
    float* invc = (float*)(smem + SM_META);
    float* bias = (float*)(smem + SM_META + 512);

    int t   = threadIdx.x;
    int wid = t >> 5, L = t & 31;
    int nh  = blockIdx.x;               // N half (0/1)
    int m0  = blockIdx.y * 128;
    int wm  = wid >> 1, wn = wid & 1;   // 4 x 2 warp grid

    if (t < 128) {
        float c = g_cnt[m0 + t];
        invc[t] = 1.0f / fmaxf(c, 1.0f);
        bias[t] = bias_l[nh * 128 + t];
    }

    // ---- per-thread ldmatrix addresses (relative to buffer base) -----------
    uint32_t aOff[2], bOff[4];
    #pragma unroll
    for (int mt = 0; mt < 2; mt++)
        aOff[mt] = (uint32_t)((wm * 32 + mt * 16 + (L & 15)) * RSTRIDE
                              + (L >> 4) * 16);
    #pragma unroll
    for (int np = 0; np < 4; np++)
        bOff[np] = (uint32_t)((wn * 64 + np * 16 + ((L >> 4) & 1) * 8 + (L & 7))
                              * RSTRIDE + ((L >> 3) & 1) * 16);

    float acc[2][8][4];
    #pragma unroll
    for (int i = 0; i < 2; i++)
        #pragma unroll
        for (int j = 0; j < 8; j++)
            #pragma unroll
            for (int q = 0; q < 4; q++) acc[i][j][q] = 0.f;

    // ---- staging helpers ----------------------------------------------------
    // A: 128 rows x 64 k fp32 -> hi/lo bf16 (8 float4 per thread)
    #define A_LOAD(REGS, CHUNK)                                                \
    {   bool fa = (CHUNK) < 4;                                                 \
        int col0 = fa ? (CHUNK) * CH : ((CHUNK) - 4) * CH;                     \
        _Pragma("unroll")                                                      \
        for (int i = 0; i < 8; i++) {                                          \
            int idx = t + i * 256;                                             \
            int row = idx >> 4, k4 = (idx & 15) << 2;                          \
            int n = m0 + row;                                                  \
            float4 v = make_float4(0.f, 0.f, 0.f, 0.f);                        \
            if (fa) v = *(const float4*)&g_agg[(size_t)n * D + col0 + k4];     \
            else if (n < N_NODES)                                              \
                v = *(const float4*)&x[(size_t)n * D + col0 + k4];             \
            REGS[i] = v;                                                       \
        }                                                                      \
    }
    #define A_STORE(REGS, BUFI, CHUNK)                                         \
    {   bool fa = (CHUNK) < 4;                                                 \
        char* bb = smem + (BUFI) * BUF;                                        \
        _Pragma("unroll")                                                      \
        for (int i = 0; i < 8; i++) {                                          \
            int idx = t + i * 256;                                             \
            int row = idx >> 4, k4 = (idx & 15) << 2;                          \
            float4 v = REGS[i];                                                \
            if (fa) {                                                          \
                float iv = invc[row];                                          \
                v.x *= iv; v.y *= iv; v.z *= iv; v.w *= iv;                    \
            }                                                                  \
            __nv_bfloat162 h01 = __floats2bfloat162_rn(v.x, v.y);              \
            __nv_bfloat162 h23 = __floats2bfloat162_rn(v.z, v.w);              \
            float lx = v.x - __bfloat162float(__low2bfloat16(h01));            \
            float ly = v.y - __bfloat162float(__high2bfloat16(h01));           \
            float lz = v.z - __bfloat162float(__low2bfloat16(h23));            \
            float lw = v.w - __bfloat162float(__high2bfloat16(h23));           \
            __nv_bfloat162 l01 = __floats2bfloat162_rn(lx, ly);                \
            __nv_bfloat162 l23 = __floats2bfloat162_rn(lz, lw);                \
            uint32_t off = (uint32_t)(row * RSTRIDE + k4 * 2);                 \
            *reinterpret_cast<uint2*>(bb + SA_HI + off) =                      \
                make_uint2(*reinterpret_cast<uint32_t*>(&h01),                 \
                           *reinterpret_cast<uint32_t*>(&h23));                \
            *reinterpret_cast<uint2*>(bb + SA_LO + off) =                      \
                make_uint2(*reinterpret_cast<uint32_t*>(&l01),                 \
                           *reinterpret_cast<uint32_t*>(&l23));                \
        }                                                                      \
    }
    // B: 128 rows x 64 k bf16 hi+lo via cp.async (4 x 16B each per thread)
    #define B_STAGE(BUFI, CHUNK)                                               \
    {   const char* gh = (const char*)g_Bhi;                                   \
        const char* gl = (const char*)g_Blo;                                   \
        uint32_t bbase = sb + (BUFI) * BUF;                                    \
        int gk0b = (CHUNK) * CH * 2;                                           \
        _Pragma("unroll")                                                      \
        for (int i = 0; i < 4; i++) {                                          \
            int idx = t + i * 256;                                             \
            int row = idx >> 3, c16 = (idx & 7) * 16;                          \
            size_t go = (size_t)(nh * 128 + row) * (KDIM * 2) + gk0b + c16;    \
            uint32_t doff = (uint32_t)(row * RSTRIDE + c16);                   \
            cp_async16(bbase + SB_HI + doff, gh + go);                         \
            cp_async16(bbase + SB_LO + doff, gl + go);                         \
        }                                                                      \
        CP_COMMIT();                                                           \
    }

    // ---- prolog: stage chunk 0 ---------------------------------------------
    float4 areg[8];
    A_LOAD(areg, 0);
    B_STAGE(0, 0);
    __syncthreads();                    // invc ready before A_STORE scaling
    A_STORE(areg, 0, 0);
    CP_WAIT0();
    __syncthreads();

    for (int c = 0; c < NCH; c++) {
        int cur = c & 1;
        if (c + 1 < NCH) {              // overlap next-chunk loads with HMMA
            A_LOAD(areg, c + 1);
            B_STAGE(cur ^ 1, c + 1);
        }
        uint32_t abase = sb + cur * BUF;
        #pragma unroll
        for (int kk = 0; kk < 4; kk++) {
            uint32_t ko = kk * 32;
            uint32_t ah[2][4], al[2][4], bh[4][4], bl[4][4];
            #pragma unroll
            for (int mt = 0; mt < 2; mt++) {
                ldsm_x4(ah[mt], abase + SA_HI + aOff[mt] + ko);
                ldsm_x4(al[mt], abase + SA_LO + aOff[mt] + ko);
            }
            #pragma unroll
            for (int np = 0; np < 4; np++) {
                ldsm_x4(bh[np], abase + SB_HI + bOff[np] + ko);
                ldsm_x4(bl[np], abase + SB_LO + bOff[np] + ko);
            }
            #pragma unroll
            for (int mt = 0; mt < 2; mt++)
                #pragma unroll
                for (int nt = 0; nt < 8; nt++) {
                    const uint32_t* bhp = &bh[nt >> 1][(nt & 1) * 2];
                    const uint32_t* blp = &bl[nt >> 1][(nt & 1) * 2];
                    mma_bf16(acc[mt][nt], ah[mt], bhp);
                    mma_bf16(acc[mt][nt], ah[mt], blp);
                    mma_bf16(acc[mt][nt], al[mt], bhp);
                }
        }
        if (c + 1 < NCH) {
            A_STORE(areg, cur ^ 1, c + 1);
            CP_WAIT0();
        }
        __syncthreads();
    }

    // ---- epilogue: bias + relu + residual + store --------------------------
    #pragma unroll
    for (int mt = 0; mt < 2; mt++) {
        #pragma unroll
        for (int nt = 0; nt < 8; nt++) {
            int nloc = wn * 64 + nt * 8 + (L & 3) * 2;
            int ncol = nh * 128 + nloc;
            float bx = bias[nloc], by = bias[nloc + 1];
            #pragma unroll
            for (int h = 0; h < 2; h++) {
                int n = m0 + wm * 32 + mt * 16 + (L >> 2) + h * 8;
                if (n < N_NODES) {
                    float2 xr = *(const float2*)&x[(size_t)n * D + ncol];
                    float2 r;
                    r.x = fmaxf(acc[mt][nt][h * 2 + 0] + bx, 0.f) + xr.x;
                    r.y = fmaxf(acc[mt][nt][h * 2 + 1] + by, 0.f) + xr.y;
                    *(float2*)&g_h1[(size_t)n * D + ncol] = r;
                }
            }
        }
    }
}

// ---------------- packed f32x2 helpers (for MLP) -----------------------------
typedef unsigned long long u64;
__device__ __forceinline__ u64 f32x2_fma(u64 a, u64 b, u64 c) {
    u64 d;
    asm("fma.rn.f32x2 %0, %1, %2, %3;" : "=l"(d) : "l"(a), "l"(b), "l"(c));
    return d;
}

// ---------------- fused MLP: 256->128->32->1 (f32x2 along K) ----------------
struct MlpSmem {
    float W1s[128][260];
    float W2s[32][132];
    float h1s[32][260];
    float h2s[32][132];
    float h3s[32][36];
    float b1s[128];
    float b2s[32];
    float W3s[32];
    float b3s;
};

__global__ __launch_bounds__(256) void mlp_kernel(
        const float* __restrict__ W1, const float* __restrict__ b1,
        const float* __restrict__ W2, const float* __restrict__ b2,
        const float* __restrict__ W3, const float* __restrict__ b3,
        float* __restrict__ out) {
    extern __shared__ MlpSmem smem_buf[];
    MlpSmem* s = smem_buf;
    int t  = threadIdx.x;
    int n0 = blockIdx.x * 32;

    const float4* W14 = (const float4*)W1;
    for (int f = t; f < 128 * 64; f += 256) {
        int o = f >> 6, k4 = f & 63;
        *(float4*)&s->W1s[o][k4 * 4] = W14[f];
    }
    const float4* W24 = (const float4*)W2;
    for (int f = t; f < 32 * 32; f += 256) {
        int o = f >> 5, k4 = f & 31;
        *(float4*)&s->W2s[o][k4 * 4] = W24[f];
    }
    const float4* h14 = (const float4*)g_h1;
    for (int f = t; f < 32 * 64; f += 256) {
        int node = f >> 6, k4 = f & 63;
        *(float4*)&s->h1s[node][k4 * 4] = h14[(size_t)(n0 + node) * 64 + k4];
    }
    if (t < 128) s->b1s[t] = b1[t];
    if (t < 32) { s->b2s[t] = b2[t]; s->W3s[t] = W3[t]; }
    if (t == 0) s->b3s = b3[0];
    __syncthreads();

    int node = t >> 3;
    int og   = t & 7;

    {   // layer 1: 256 -> 128
        u64 acc[16];
        #pragma unroll
        for (int j = 0; j < 16; j++) acc[j] = 0ull;
        for (int k4 = 0; k4 < 64; k4++) {
            ulonglong2 h = *(const ulonglong2*)&s->h1s[node][k4 * 4];
            #pragma unroll
            for (int j = 0; j < 16; j++) {
                ulonglong2 w = *(const ulonglong2*)&s->W1s[og + 8 * j][k4 * 4];
                acc[j] = f32x2_fma(h.x, w.x, acc[j]);
                acc[j] = f32x2_fma(h.y, w.y, acc[j]);
            }
        }
        #pragma unroll
        for (int j = 0; j < 16; j++) {
            float2 a = *(float2*)&acc[j];
            s->h2s[node][og + 8 * j] = fmaxf(a.x + a.y + s->b1s[og + 8 * j], 0.f);
        }
    }
    __syncthreads();

    {   // layer 2: 128 -> 32
        u64 acc[4];
        #pragma unroll
        for (int j = 0; j < 4; j++) acc[j] = 0ull;
        for (int k4 = 0; k4 < 32; k4++) {
            ulonglong2 h = *(const ulonglong2*)&s->h2s[node][k4 * 4];
            #pragma unroll
            for (int j = 0; j < 4; j++) {
                ulonglong2 w = *(const ulonglong2*)&s->W2s[og + 8 * j][k4 * 4];
                acc[j] = f32x2_fma(h.x, w.x, acc[j]);
                acc[j] = f32x2_fma(h.y, w.y, acc[j]);
            }
        }
        #pragma unroll
        for (int j = 0; j < 4; j++) {
            float2 a = *(float2*)&acc[j];
            s->h3s[node][og + 8 * j] = fmaxf(a.x + a.y + s->b2s[og + 8 * j], 0.f);
        }
    }
    __syncthreads();

    // layer 3: 32 -> 1
    if (t < 32) {
        int n = n0 + t;
        if (n < N_NODES) {
            float v = s->b3s;
            #pragma unroll
            for (int k = 0; k < 32; k++) v += s->h3s[t][k] * s->W3s[k];
            out[n] = v;
        }
    }
}

// ---------------- launch -----------------------------------------------------
extern "C" void kernel_launch(void* const* d_in, const int* in_sizes, int n_in,
                              void* d_out, int out_size) {
    const float*     x  = (const float*)d_in[0];
    const long long* ei = (const long long*)d_in[1];
    const float*     Wl = (const float*)d_in[2];
    const float*     bl = (const float*)d_in[3];
    const float*     Wr = (const float*)d_in[4];
    const float*     W1 = (const float*)d_in[5];
    const float*     b1 = (const float*)d_in[6];
    const float*     W2 = (const float*)d_in[7];
    const float*     b2 = (const float*)d_in[8];
    const float*     W3 = (const float*)d_in[9];
    const float*     b3 = (const float*)d_in[10];
    float* out = (float*)d_out;

    zero_kernel<<<2048, 256>>>();
    detect_kernel<<<1, 32>>>((const int*)ei);
    prep_kernel<<<512, 256>>>(Wl, Wr);
    scatter_kernel<<<(N_EDGES * 8 + 255) / 256, 256>>>((const float4*)x, ei);

    cudaFuncSetAttribute(conv_kernel, cudaFuncAttributeMaxDynamicSharedMemorySize,
                         CONV_SMEM);
    conv_kernel<<<dim3(2, NPAD / 128), 256, CONV_SMEM>>>(x, bl);

    cudaFuncSetAttribute(mlp_kernel, cudaFuncAttributeMaxDynamicSharedMemorySize,
                         (int)sizeof(MlpSmem));
    mlp_kernel<<<NPAD / 32, 256, sizeof(MlpSmem)>>>(W1, b1, W2, b2, W3, b3, out);
}

// round 10
// speedup vs baseline: 1.5291x; 1.0020x over previous
#include <cuda_runtime.h>
#include <cuda_bf16.h>
#include <cstdint>

#define N_NODES 100000
#define NPAD    100096          // multiple of 128 (conv tile) and 32 (mlp)
#define N_EDGES 800000
#define D       256
#define KDIM    512             // GEMM K = 2*D  ([mean | x])

// ---------------- scratch (device globals: no allocations allowed) ----------
__device__ __align__(16) float g_agg[(size_t)NPAD * D];   // ~102.5 MB
__device__ float g_cnt[NPAD];
__device__ __align__(16) float g_h1[(size_t)NPAD * D];    // ~102.5 MB
__device__ int   g_is64;
__device__ __align__(16) __nv_bfloat16 g_Bhi[256 * KDIM]; // 256 KB
__device__ __align__(16) __nv_bfloat16 g_Blo[256 * KDIM]; // 256 KB

// ---------------- zero scratch ----------------------------------------------
__global__ void zero_kernel() {
    int i = blockIdx.x * blockDim.x + threadIdx.x;
    int stride = gridDim.x * blockDim.x;
    float4 z = make_float4(0.f, 0.f, 0.f, 0.f);
    float4* a4 = reinterpret_cast<float4*>(g_agg);
    const int n4 = NPAD * (D / 4);
    for (int j = i; j < n4; j += stride) a4[j] = z;
    for (int j = i; j < NPAD; j += stride) g_cnt[j] = 0.f;
}

// ---------------- int32 vs int64 edge_index detection -----------------------
__global__ void detect_kernel(const int* __restrict__ ei32) {
    if (blockIdx.x == 0 && threadIdx.x == 0) {
        int odd_or = 0;
        #pragma unroll 8
        for (int i = 0; i < 64; i++) odd_or |= ei32[2 * i + 1];
        g_is64 = (odd_or == 0) ? 1 : 0;
    }
}

// ---------------- B prep: split [Wl | Wr] into bf16 hi/lo --------------------
__global__ void prep_kernel(const float* __restrict__ Wl, const float* __restrict__ Wr) {
    int idx = blockIdx.x * 256 + threadIdx.x;      // 256*512 = 131072 total
    int o = idx >> 9, k = idx & 511;
    float w = (k < 256) ? Wl[o * 256 + k] : Wr[o * 256 + (k - 256)];
    __nv_bfloat16 hi = __float2bfloat16(w);
    __nv_bfloat16 lo = __float2bfloat16(w - __bfloat162float(hi));
    g_Bhi[idx] = hi;
    g_Blo[idx] = lo;
}

// ---------------- scatter-add aggregation -----------------------------------
__device__ __forceinline__ void red_add_v4(float4* p, float4 v) {
    asm volatile("red.global.add.v4.f32 [%0], {%1, %2, %3, %4};"
                 :: "l"(p), "f"(v.x), "f"(v.y), "f"(v.z), "f"(v.w)
                 : "memory");
}

__global__ __launch_bounds__(256) void scatter_kernel(
        const float4* __restrict__ x4, const long long* __restrict__ ei64) {
    int t = blockIdx.x * blockDim.x + threadIdx.x;
    int e  = t >> 3;
    int c0 = t & 7;
    if (e >= N_EDGES) return;
    int src, dst;
    if (g_is64) {
        src = (int)ei64[e];
        dst = (int)ei64[N_EDGES + e];
    } else {
        const int* p = (const int*)ei64;
        src = p[e];
        dst = p[N_EDGES + e];
    }
    const float4* xr = x4 + (size_t)src * (D / 4);
    float4*       ar = reinterpret_cast<float4*>(g_agg) + (size_t)dst * (D / 4);
    float4 v[8];
    #pragma unroll
    for (int i = 0; i < 8; i++) v[i] = __ldg(&xr[c0 + 8 * i]);
    #pragma unroll
    for (int i = 0; i < 8; i++) red_add_v4(&ar[c0 + 8 * i], v[i]);
    if (c0 == 0) atomicAdd(&g_cnt[dst], 1.0f);
}

// ---------------- mma.sync helpers -------------------------------------------
__device__ __forceinline__ uint32_t smem_u32(const void* p) {
    uint32_t a;
    asm("{ .reg .u64 t; cvta.to.shared.u64 t, %1; cvt.u32.u64 %0, t; }"
        : "=r"(a) : "l"(p));
    return a;
}
__device__ __forceinline__ void ldsm_x4(uint32_t* r, uint32_t addr) {
    asm volatile("ldmatrix.sync.aligned.m8n8.x4.shared.b16 {%0,%1,%2,%3}, [%4];"
                 : "=r"(r[0]), "=r"(r[1]), "=r"(r[2]), "=r"(r[3]) : "r"(addr));
}
__device__ __forceinline__ void mma_bf16(float* d, const uint32_t* a,
                                         const uint32_t* b) {
    asm volatile("mma.sync.aligned.m16n8k16.row.col.f32.bf16.bf16.f32 "
                 "{%0,%1,%2,%3}, {%4,%5,%6,%7}, {%8,%9}, {%0,%1,%2,%3};"
                 : "+f"(d[0]), "+f"(d[1]), "+f"(d[2]), "+f"(d[3])
                 : "r"(a[0]), "r"(a[1]), "r"(a[2]), "r"(a[3]),
                   "r"(b[0]), "r"(b[1]));
}
__device__ __forceinline__ void cp_async16(uint32_t dst, const void* src) {
    asm volatile("cp.async.cg.shared.global [%0], [%1], 16;"
                 :: "r"(dst), "l"(src) : "memory");
}
#define CP_COMMIT() asm volatile("cp.async.commit_group;" ::: "memory")
#define CP_WAIT0()  asm volatile("cp.async.wait_group 0;" ::: "memory")

// ---------------- SAGEConv via mma.sync bf16-split ---------------------------
// C[128 x 128] = A[128 x 512] * B[128 x 512]^T per CTA (2 N-halves)
// A = [mean | x] (fp32 -> hi/lo bf16 in-flight),  B = [Wl | Wr] pre-split.
// 3 terms: Ahi*Bhi + Ahi*Blo + Alo*Bhi.
#define CH       64
#define NCH      (KDIM / CH)    // 8
#define RSTRIDE  144            // bytes per smem row (72 bf16, conflict-free)
#define SA_HI    0
#define SA_LO    18432
#define SB_HI    36864
#define SB_LO    55296
#define BUF      73728
#define SM_META  (2 * BUF)      // invc[128] then bias[128]
#define CONV_SMEM (SM_META + 1024)

__global__ __launch_bounds__(256) void conv_kernel(
        const float* __restrict__ x, const float* __restrict__ bias_l) {
    extern __shared__ char smem[];
    uint32_t sb = smem_u32(smem);
    float* invc = (float*)(smem + SM_META);
    float* bias = (float*)(smem + SM_META + 512);

    int t   = threadIdx.x;
    int wid = t >> 5, L = t & 31;
    int nh  = blockIdx.x;               // N half (0/1)
    int m0  = blockIdx.y * 128;
    int wm  = wid >> 1, wn = wid & 1;   // 4 x 2 warp grid

    if (t < 128) {
        float c = g_cnt[m0 + t];
        invc[t] = 1.0f / fmaxf(c, 1.0f);
        bias[t] = bias_l[nh * 128 + t];
    }

    // ---- per-thread ldmatrix addresses (relative to buffer base) -----------
    uint32_t aOff[2], bOff[4];
    #pragma unroll
    for (int mt = 0; mt < 2; mt++)
        aOff[mt] = (uint32_t)((wm * 32 + mt * 16 + (L & 15)) * RSTRIDE
                              + (L >> 4) * 16);
    #pragma unroll
    for (int np = 0; np < 4; np++)
        bOff[np] = (uint32_t)((wn * 64 + np * 16 + ((L >> 4) & 1) * 8 + (L & 7))
                              * RSTRIDE + ((L >> 3) & 1) * 16);

    float acc[2][8][4];
    #pragma unroll
    for (int i = 0; i < 2; i++)
        #pragma unroll
        for (int j = 0; j < 8; j++)
            #pragma unroll
            for (int q = 0; q < 4; q++) acc[i][j][q] = 0.f;

    // ---- staging helpers ----------------------------------------------------
    // A: 128 rows x 64 k fp32 -> hi/lo bf16 (8 float4 per thread)
    #define A_LOAD(REGS, CHUNK)                                                \
    {   bool fa = (CHUNK) < 4;                                                 \
        int col0 = fa ? (CHUNK) * CH : ((CHUNK) - 4) * CH;                     \
        _Pragma("unroll")                                                      \
        for (int i = 0; i < 8; i++) {                                          \
            int idx = t + i * 256;                                             \
            int row = idx >> 4, k4 = (idx & 15) << 2;                          \
            int n = m0 + row;                                                  \
            float4 v = make_float4(0.f, 0.f, 0.f, 0.f);                        \
            if (fa) v = *(const float4*)&g_agg[(size_t)n * D + col0 + k4];     \
            else if (n < N_NODES)                                              \
                v = *(const float4*)&x[(size_t)n * D + col0 + k4];             \
            REGS[i] = v;                                                       \
        }                                                                      \
    }
    #define A_STORE(REGS, BUFI, CHUNK)                                         \
    {   bool fa = (CHUNK) < 4;                                                 \
        char* bb = smem + (BUFI) * BUF;                                        \
        _Pragma("unroll")                                                      \
        for (int i = 0; i < 8; i++) {                                          \
            int idx = t + i * 256;                                             \
            int row = idx >> 4, k4 = (idx & 15) << 2;                          \
            float4 v = REGS[i];                                                \
            if (fa) {                                                          \
                float iv = invc[row];                                          \
                v.x *= iv; v.y *= iv; v.z *= iv; v.w *= iv;                    \
            }                                                                  \
            __nv_bfloat162 h01 = __floats2bfloat162_rn(v.x, v.y);              \
            __nv_bfloat162 h23 = __floats2bfloat162_rn(v.z, v.w);              \
            float lx = v.x - __bfloat162float(__low2bfloat16(h01));            \
            float ly = v.y - __bfloat162float(__high2bfloat16(h01));           \
            float lz = v.z - __bfloat162float(__low2bfloat16(h23));            \
            float lw = v.w - __bfloat162float(__high2bfloat16(h23));           \
            __nv_bfloat162 l01 = __floats2bfloat162_rn(lx, ly);                \
            __nv_bfloat162 l23 = __floats2bfloat162_rn(lz, lw);                \
            uint32_t off = (uint32_t)(row * RSTRIDE + k4 * 2);                 \
            *reinterpret_cast<uint2*>(bb + SA_HI + off) =                      \
                make_uint2(*reinterpret_cast<uint32_t*>(&h01),                 \
                           *reinterpret_cast<uint32_t*>(&h23));                \
            *reinterpret_cast<uint2*>(bb + SA_LO + off) =                      \
                make_uint2(*reinterpret_cast<uint32_t*>(&l01),                 \
                           *reinterpret_cast<uint32_t*>(&l23));                \
        }                                                                      \
    }
    // B: 128 rows x 64 k bf16 hi+lo via cp.async (4 x 16B each per thread)
    #define B_STAGE(BUFI, CHUNK)                                               \
    {   const char* gh = (const char*)g_Bhi;                                   \
        const char* gl = (const char*)g_Blo;                                   \
        uint32_t bbase = sb + (BUFI) * BUF;                                    \
        int gk0b = (CHUNK) * CH * 2;                                           \
        _Pragma("unroll")                                                      \
        for (int i = 0; i < 4; i++) {                                          \
            int idx = t + i * 256;                                             \
            int row = idx >> 3, c16 = (idx & 7) * 16;                          \
            size_t go = (size_t)(nh * 128 + row) * (KDIM * 2) + gk0b + c16;    \
            uint32_t doff = (uint32_t)(row * RSTRIDE + c16);                   \
            cp_async16(bbase + SB_HI + doff, gh + go);                         \
            cp_async16(bbase + SB_LO + doff, gl + go);                         \
        }                                                                      \
        CP_COMMIT();                                                           \
    }

    // ---- prolog: stage chunk 0 ---------------------------------------------
    float4 areg[8];
    A_LOAD(areg, 0);
    B_STAGE(0, 0);
    __syncthreads();                    // invc ready before A_STORE scaling
    A_STORE(areg, 0, 0);
    CP_WAIT0();
    __syncthreads();

    for (int c = 0; c < NCH; c++) {
        int cur = c & 1;
        if (c + 1 < NCH) {              // overlap next-chunk loads with HMMA
            A_LOAD(areg, c + 1);
            B_STAGE(cur ^ 1, c + 1);
        }
        uint32_t abase = sb + cur * BUF;
        #pragma unroll
        for (int kk = 0; kk < 4; kk++) {
            uint32_t ko = kk * 32;
            uint32_t ah[2][4], al[2][4], bh[4][4], bl[4][4];
            #pragma unroll
            for (int mt = 0; mt < 2; mt++) {
                ldsm_x4(ah[mt], abase + SA_HI + aOff[mt] + ko);
                ldsm_x4(al[mt], abase + SA_LO + aOff[mt] + ko);
            }
            #pragma unroll
            for (int np = 0; np < 4; np++) {
                ldsm_x4(bh[np], abase + SB_HI + bOff[np] + ko);
                ldsm_x4(bl[np], abase + SB_LO + bOff[np] + ko);
            }
            #pragma unroll
            for (int mt = 0; mt < 2; mt++)
                #pragma unroll
                for (int nt = 0; nt < 8; nt++) {
                    const uint32_t* bhp = &bh[nt >> 1][(nt & 1) * 2];
                    const uint32_t* blp = &bl[nt >> 1][(nt & 1) * 2];
                    mma_bf16(acc[mt][nt], ah[mt], bhp);
                    mma_bf16(acc[mt][nt], ah[mt], blp);
                    mma_bf16(acc[mt][nt], al[mt], bhp);
                }
        }
        if (c + 1 < NCH) {
            A_STORE(areg, cur ^ 1, c + 1);
            CP_WAIT0();
        }
        __syncthreads();
    }

    // ---- epilogue: bias + relu + residual + store --------------------------
    #pragma unroll
    for (int mt = 0; mt < 2; mt++) {
        #pragma unroll
        for (int nt = 0; nt < 8; nt++) {
            int nloc = wn * 64 + nt * 8 + (L & 3) * 2;
            int ncol = nh * 128 + nloc;
            float bx = bias[nloc], by = bias[nloc + 1];
            #pragma unroll
            for (int h = 0; h < 2; h++) {
                int n = m0 + wm * 32 + mt * 16 + (L >> 2) + h * 8;
                if (n < N_NODES) {
                    float2 xr = *(const float2*)&x[(size_t)n * D + ncol];
                    float2 r;
                    r.x = fmaxf(acc[mt][nt][h * 2 + 0] + bx, 0.f) + xr.x;
                    r.y = fmaxf(acc[mt][nt][h * 2 + 1] + by, 0.f) + xr.y;
                    *(float2*)&g_h1[(size_t)n * D + ncol] = r;
                }
            }
        }
    }
}

// ---------------- packed f32x2 helpers (for MLP) -----------------------------
typedef unsigned long long u64;
__device__ __forceinline__ u64 f32x2_fma(u64 a, u64 b, u64 c) {
    u64 d;
    asm("fma.rn.f32x2 %0, %1, %2, %3;" : "=l"(d) : "l"(a), "l"(b), "l"(c));
    return d;
}

// ---------------- fused MLP: 256->128->32->1 (f32x2 along K) ----------------
struct MlpSmem {
    float W1s[128][260];
    float W2s[32][132];
    float h1s[32][260];
    float h2s[32][132];
    float h3s[32][36];
    float b1s[128];
    float b2s[32];
    float W3s[32];
    float b3s;
};

__global__ __launch_bounds__(256) void mlp_kernel(
        const float* __restrict__ W1, const float* __restrict__ b1,
        const float* __restrict__ W2, const float* __restrict__ b2,
        const float* __restrict__ W3, const float* __restrict__ b3,
        float* __restrict__ out) {
    extern __shared__ MlpSmem smem_buf[];
    MlpSmem* s = smem_buf;
    int t  = threadIdx.x;
    int n0 = blockIdx.x * 32;

    const float4* W14 = (const float4*)W1;
    for (int f = t; f < 128 * 64; f += 256) {
        int o = f >> 6, k4 = f & 63;
        *(float4*)&s->W1s[o][k4 * 4] = W14[f];
    }
    const float4* W24 = (const float4*)W2;
    for (int f = t; f < 32 * 32; f += 256) {
        int o = f >> 5, k4 = f & 31;
        *(float4*)&s->W2s[o][k4 * 4] = W24[f];
    }
    const float4* h14 = (const float4*)g_h1;
    for (int f = t; f < 32 * 64; f += 256) {
        int node = f >> 6, k4 = f & 63;
        *(float4*)&s->h1s[node][k4 * 4] = h14[(size_t)(n0 + node) * 64 + k4];
    }
    if (t < 128) s->b1s[t] = b1[t];
    if (t < 32) { s->b2s[t] = b2[t]; s->W3s[t] = W3[t]; }
    if (t == 0) s->b3s = b3[0];
    __syncthreads();

    int node = t >> 3;
    int og   = t & 7;

    {   // layer 1: 256 -> 128
        u64 acc[16];
        #pragma unroll
        for (int j = 0; j < 16; j++) acc[j] = 0ull;
        for (int k4 = 0; k4 < 64; k4++) {
            ulonglong2 h = *(const ulonglong2*)&s->h1s[node][k4 * 4];
            #pragma unroll
            for (int j = 0; j < 16; j++) {
                ulonglong2 w = *(const ulonglong2*)&s->W1s[og + 8 * j][k4 * 4];
                acc[j] = f32x2_fma(h.x, w.x, acc[j]);
                acc[j] = f32x2_fma(h.y, w.y, acc[j]);
            }
        }
        #pragma unroll
        for (int j = 0; j < 16; j++) {
            float2 a = *(float2*)&acc[j];
            s->h2s[node][og + 8 * j] = fmaxf(a.x + a.y + s->b1s[og + 8 * j], 0.f);
        }
    }
    __syncthreads();

    {   // layer 2: 128 -> 32
        u64 acc[4];
        #pragma unroll
        for (int j = 0; j < 4; j++) acc[j] = 0ull;
        for (int k4 = 0; k4 < 32; k4++) {
            ulonglong2 h = *(const ulonglong2*)&s->h2s[node][k4 * 4];
            #pragma unroll
            for (int j = 0; j < 4; j++) {
                ulonglong2 w = *(const ulonglong2*)&s->W2s[og + 8 * j][k4 * 4];
                acc[j] = f32x2_fma(h.x, w.x, acc[j]);
                acc[j] = f32x2_fma(h.y, w.y, acc[j]);
            }
        }
        #pragma unroll
        for (int j = 0; j < 4; j++) {
            float2 a = *(float2*)&acc[j];
            s->h3s[node][og + 8 * j] = fmaxf(a.x + a.y + s->b2s[og + 8 * j], 0.f);
        }
    }
    __syncthreads();

    // layer 3: 32 -> 1
    if (t < 32) {
        int n = n0 + t;
        if (n < N_NODES) {
            float v = s->b3s;
            #pragma unroll
            for (int k = 0; k < 32; k++) v += s->h3s[t][k] * s->W3s[k];
            out[n] = v;
        }
    }
}

// ---------------- launch -----------------------------------------------------
extern "C" void kernel_launch(void* const* d_in, const int* in_sizes, int n_in,
                              void* d_out, int out_size) {
    const float*     x  = (const float*)d_in[0];
    const long long* ei = (const long long*)d_in[1];
    const float*     Wl = (const float*)d_in[2];
    const float*     bl = (const float*)d_in[3];
    const float*     Wr = (const float*)d_in[4];
    const float*     W1 = (const float*)d_in[5];
    const float*     b1 = (const float*)d_in[6];
    const float*     W2 = (const float*)d_in[7];
    const float*     b2 = (const float*)d_in[8];
    const float*     W3 = (const float*)d_in[9];
    const float*     b3 = (const float*)d_in[10];
    float* out = (float*)d_out;

    zero_kernel<<<2048, 256>>>();
    detect_kernel<<<1, 32>>>((const int*)ei);
    prep_kernel<<<512, 256>>>(Wl, Wr);
    scatter_kernel<<<(N_EDGES * 8 + 255) / 256, 256>>>((const float4*)x, ei);

    cudaFuncSetAttribute(conv_kernel, cudaFuncAttributeMaxDynamicSharedMemorySize,
                         CONV_SMEM);
    conv_kernel<<<dim3(2, NPAD / 128), 256, CONV_SMEM>>>(x, bl);

    cudaFuncSetAttribute(mlp_kernel, cudaFuncAttributeMaxDynamicSharedMemorySize,
                         (int)sizeof(MlpSmem));
    mlp_kernel<<<NPAD / 32, 256, sizeof(MlpSmem)>>>(W1, b1, W2, b2, W3, b3, out);
}

// round 11
// speedup vs baseline: 1.5342x; 1.0034x over previous
#include <cuda_runtime.h>
#include <cuda_bf16.h>
#include <cstdint>

#define N_NODES 100000
#define NPAD    100096          // multiple of 128 (conv tile) and 32 (mlp)
#define N_EDGES 800000
#define D       256
#define KDIM    512             // GEMM K = 2*D  ([mean | x])

// ---------------- scratch (device globals: no allocations allowed) ----------
__device__ __align__(16) float g_agg[(size_t)NPAD * D];   // ~102.5 MB
__device__ float g_cnt[NPAD];
__device__ __align__(16) float g_h1[(size_t)NPAD * D];    // ~102.5 MB
__device__ int   g_is64;
__device__ __align__(16) __nv_bfloat16 g_Bhi[256 * KDIM]; // 256 KB
__device__ __align__(16) __nv_bfloat16 g_Blo[256 * KDIM]; // 256 KB

// ---------------- zero scratch ----------------------------------------------
__global__ void zero_kernel() {
    int i = blockIdx.x * blockDim.x + threadIdx.x;
    int stride = gridDim.x * blockDim.x;
    float4 z = make_float4(0.f, 0.f, 0.f, 0.f);
    float4* a4 = reinterpret_cast<float4*>(g_agg);
    const int n4 = NPAD * (D / 4);
    for (int j = i; j < n4; j += stride) a4[j] = z;
    for (int j = i; j < NPAD; j += stride) g_cnt[j] = 0.f;
}

// ---------------- int32 vs int64 edge_index detection -----------------------
__global__ void detect_kernel(const int* __restrict__ ei32) {
    if (blockIdx.x == 0 && threadIdx.x == 0) {
        int odd_or = 0;
        #pragma unroll 8
        for (int i = 0; i < 64; i++) odd_or |= ei32[2 * i + 1];
        g_is64 = (odd_or == 0) ? 1 : 0;
    }
}

// ---------------- B prep: split [Wl | Wr] into bf16 hi/lo --------------------
__global__ void prep_kernel(const float* __restrict__ Wl, const float* __restrict__ Wr) {
    int idx = blockIdx.x * 256 + threadIdx.x;      // 256*512 = 131072 total
    int o = idx >> 9, k = idx & 511;
    float w = (k < 256) ? Wl[o * 256 + k] : Wr[o * 256 + (k - 256)];
    __nv_bfloat16 hi = __float2bfloat16(w);
    __nv_bfloat16 lo = __float2bfloat16(w - __bfloat162float(hi));
    g_Bhi[idx] = hi;
    g_Blo[idx] = lo;
}

// ---------------- scatter-add aggregation -----------------------------------
__device__ __forceinline__ void red_add_v4(float4* p, float4 v) {
    asm volatile("red.global.add.v4.f32 [%0], {%1, %2, %3, %4};"
                 :: "l"(p), "f"(v.x), "f"(v.y), "f"(v.z), "f"(v.w)
                 : "memory");
}

__global__ __launch_bounds__(256) void scatter_kernel(
        const float4* __restrict__ x4, const long long* __restrict__ ei64) {
    int t = blockIdx.x * blockDim.x + threadIdx.x;
    int e  = t >> 3;
    int c0 = t & 7;
    if (e >= N_EDGES) return;
    int src, dst;
    if (g_is64) {
        src = (int)ei64[e];
        dst = (int)ei64[N_EDGES + e];
    } else {
        const int* p = (const int*)ei64;
        src = p[e];
        dst = p[N_EDGES + e];
    }
    const float4* xr = x4 + (size_t)src * (D / 4);
    float4*       ar = reinterpret_cast<float4*>(g_agg) + (size_t)dst * (D / 4);
    float4 v[8];
    #pragma unroll
    for (int i = 0; i < 8; i++) v[i] = __ldg(&xr[c0 + 8 * i]);
    #pragma unroll
    for (int i = 0; i < 8; i++) red_add_v4(&ar[c0 + 8 * i], v[i]);
    if (c0 == 0) atomicAdd(&g_cnt[dst], 1.0f);
}

// ---------------- mma.sync helpers -------------------------------------------
__device__ __forceinline__ uint32_t smem_u32(const void* p) {
    uint32_t a;
    asm("{ .reg .u64 t; cvta.to.shared.u64 t, %1; cvt.u32.u64 %0, t; }"
        : "=r"(a) : "l"(p));
    return a;
}
__device__ __forceinline__ void ldsm_x4(uint32_t* r, uint32_t addr) {
    asm volatile("ldmatrix.sync.aligned.m8n8.x4.shared.b16 {%0,%1,%2,%3}, [%4];"
                 : "=r"(r[0]), "=r"(r[1]), "=r"(r[2]), "=r"(r[3]) : "r"(addr));
}
__device__ __forceinline__ void mma_bf16(float* d, const uint32_t* a,
                                         const uint32_t* b) {
    asm volatile("mma.sync.aligned.m16n8k16.row.col.f32.bf16.bf16.f32 "
                 "{%0,%1,%2,%3}, {%4,%5,%6,%7}, {%8,%9}, {%0,%1,%2,%3};"
                 : "+f"(d[0]), "+f"(d[1]), "+f"(d[2]), "+f"(d[3])
                 : "r"(a[0]), "r"(a[1]), "r"(a[2]), "r"(a[3]),
                   "r"(b[0]), "r"(b[1]));
}
__device__ __forceinline__ void cp_async16(uint32_t dst, const void* src) {
    asm volatile("cp.async.cg.shared.global [%0], [%1], 16;"
                 :: "r"(dst), "l"(src) : "memory");
}
#define CP_COMMIT() asm volatile("cp.async.commit_group;" ::: "memory")
#define CP_WAIT0()  asm volatile("cp.async.wait_group 0;" ::: "memory")

// ---------------- SAGEConv via mma.sync bf16-split ---------------------------
// C[128 x 128] = A[128 x 512] * B[128 x 512]^T per CTA (2 N-halves)
// A = [mean | x] (fp32 -> hi/lo bf16 in-flight),  B = [Wl | Wr] pre-split.
// 3 terms: Ahi*Bhi + Ahi*Blo + Alo*Bhi.
#define CH       64
#define NCH      (KDIM / CH)    // 8
#define RSTRIDE  144            // bytes per smem row (72 bf16, conflict-free)
#define SA_HI    0
#define SA_LO    18432
#define SB_HI    36864
#define SB_LO    55296
#define BUF      73728
#define SM_META  (2 * BUF)      // invc[128] then bias[128]
#define CONV_SMEM (SM_META + 1024)

__global__ __launch_bounds__(256) void conv_kernel(
        const float* __restrict__ x, const float* __restrict__ bias_l) {
    extern __shared__ char smem[];
    uint32_t sb = smem_u32(smem);
    float* invc = (float*)(smem + SM_META);
    float* bias = (float*)(smem + SM_META + 512);

    int t   = threadIdx.x;
    int wid = t >> 5, L = t & 31;
    int nh  = blockIdx.x;               // N half (0/1)
    int m0  = blockIdx.y * 128;
    int wm  = wid >> 1, wn = wid & 1;   // 4 x 2 warp grid

    if (t < 128) {
        float c = g_cnt[m0 + t];
        invc[t] = 1.0f / fmaxf(c, 1.0f);
        bias[t] = bias_l[nh * 128 + t];
    }

    // ---- per-thread ldmatrix addresses (relative to buffer base) -----------
    uint32_t aOff[2], bOff[4];
    #pragma unroll
    for (int mt = 0; mt < 2; mt++)
        aOff[mt] = (uint32_t)((wm * 32 + mt * 16 + (L & 15)) * RSTRIDE
                              + (L >> 4) * 16);
    #pragma unroll
    for (int np = 0; np < 4; np++)
        bOff[np] = (uint32_t)((wn * 64 + np * 16 + ((L >> 4) & 1) * 8 + (L & 7))
                              * RSTRIDE + ((L >> 3) & 1) * 16);

    float acc[2][8][4];
    #pragma unroll
    for (int i = 0; i < 2; i++)
        #pragma unroll
        for (int j = 0; j < 8; j++)
            #pragma unroll
            for (int q = 0; q < 4; q++) acc[i][j][q] = 0.f;

    // ---- staging helpers ----------------------------------------------------
    // A: 128 rows x 64 k fp32 -> hi/lo bf16 (8 float4 per thread)
    #define A_LOAD(REGS, CHUNK)                                                \
    {   bool fa = (CHUNK) < 4;                                                 \
        int col0 = fa ? (CHUNK) * CH : ((CHUNK) - 4) * CH;                     \
        _Pragma("unroll")                                                      \
        for (int i = 0; i < 8; i++) {                                          \
            int idx = t + i * 256;                                             \
            int row = idx >> 4, k4 = (idx & 15) << 2;                          \
            int n = m0 + row;                                                  \
            float4 v = make_float4(0.f, 0.f, 0.f, 0.f);                        \
            if (fa) v = *(const float4*)&g_agg[(size_t)n * D + col0 + k4];     \
            else if (n < N_NODES)                                              \
                v = *(const float4*)&x[(size_t)n * D + col0 + k4];             \
            REGS[i] = v;                                                       \
        }                                                                      \
    }
    #define A_STORE(REGS, BUFI, CHUNK)                                         \
    {   bool fa = (CHUNK) < 4;                                                 \
        char* bb = smem + (BUFI) * BUF;                                        \
        _Pragma("unroll")                                                      \
        for (int i = 0; i < 8; i++) {                                          \
            int idx = t + i * 256;                                             \
            int row = idx >> 4, k4 = (idx & 15) << 2;                          \
            float4 v = REGS[i];                                                \
            if (fa) {                                                          \
                float iv = invc[row];                                          \
                v.x *= iv; v.y *= iv; v.z *= iv; v.w *= iv;                    \
            }                                                                  \
            __nv_bfloat162 h01 = __floats2bfloat162_rn(v.x, v.y);              \
            __nv_bfloat162 h23 = __floats2bfloat162_rn(v.z, v.w);              \
            float lx = v.x - __bfloat162float(__low2bfloat16(h01));            \
            float ly = v.y - __bfloat162float(__high2bfloat16(h01));           \
            float lz = v.z - __bfloat162float(__low2bfloat16(h23));            \
            float lw = v.w - __bfloat162float(__high2bfloat16(h23));           \
            __nv_bfloat162 l01 = __floats2bfloat162_rn(lx, ly);                \
            __nv_bfloat162 l23 = __floats2bfloat162_rn(lz, lw);                \
            uint32_t off = (uint32_t)(row * RSTRIDE + k4 * 2);                 \
            *reinterpret_cast<uint2*>(bb + SA_HI + off) =                      \
                make_uint2(*reinterpret_cast<uint32_t*>(&h01),                 \
                           *reinterpret_cast<uint32_t*>(&h23));                \
            *reinterpret_cast<uint2*>(bb + SA_LO + off) =                      \
                make_uint2(*reinterpret_cast<uint32_t*>(&l01),                 \
                           *reinterpret_cast<uint32_t*>(&l23));                \
        }                                                                      \
    }
    // B: 128 rows x 64 k bf16 hi+lo via cp.async (4 x 16B each per thread)
    #define B_STAGE(BUFI, CHUNK)                                               \
    {   const char* gh = (const char*)g_Bhi;                                   \
        const char* gl = (const char*)g_Blo;                                   \
        uint32_t bbase = sb + (BUFI) * BUF;                                    \
        int gk0b = (CHUNK) * CH * 2;                                           \
        _Pragma("unroll")                                                      \
        for (int i = 0; i < 4; i++) {                                          \
            int idx = t + i * 256;                                             \
            int row = idx >> 3, c16 = (idx & 7) * 16;                          \
            size_t go = (size_t)(nh * 128 + row) * (KDIM * 2) + gk0b + c16;    \
            uint32_t doff = (uint32_t)(row * RSTRIDE + c16);                   \
            cp_async16(bbase + SB_HI + doff, gh + go);                         \
            cp_async16(bbase + SB_LO + doff, gl + go);                         \
        }                                                                      \
        CP_COMMIT();                                                           \
    }

    // ---- prolog: stage chunk 0 ---------------------------------------------
    float4 areg[8];
    A_LOAD(areg, 0);
    B_STAGE(0, 0);
    __syncthreads();                    // invc ready before A_STORE scaling
    A_STORE(areg, 0, 0);
    CP_WAIT0();
    __syncthreads();

    for (int c = 0; c < NCH; c++) {
        int cur = c & 1;
        if (c + 1 < NCH) {              // overlap next-chunk loads with HMMA
            A_LOAD(areg, c + 1);
            B_STAGE(cur ^ 1, c + 1);
        }
        uint32_t abase = sb + cur * BUF;
        #pragma unroll
        for (int kk = 0; kk < 4; kk++) {
            uint32_t ko = kk * 32;
            uint32_t ah[2][4], al[2][4], bh[4][4], bl[4][4];
            #pragma unroll
            for (int mt = 0; mt < 2; mt++) {
                ldsm_x4(ah[mt], abase + SA_HI + aOff[mt] + ko);
                ldsm_x4(al[mt], abase + SA_LO + aOff[mt] + ko);
            }
            #pragma unroll
            for (int np = 0; np < 4; np++) {
                ldsm_x4(bh[np], abase + SB_HI + bOff[np] + ko);
                ldsm_x4(bl[np], abase + SB_LO + bOff[np] + ko);
            }
            #pragma unroll
            for (int mt = 0; mt < 2; mt++)
                #pragma unroll
                for (int nt = 0; nt < 8; nt++) {
                    const uint32_t* bhp = &bh[nt >> 1][(nt & 1) * 2];
                    const uint32_t* blp = &bl[nt >> 1][(nt & 1) * 2];
                    mma_bf16(acc[mt][nt], ah[mt], bhp);
                    mma_bf16(acc[mt][nt], ah[mt], blp);
                    mma_bf16(acc[mt][nt], al[mt], bhp);
                }
        }
        if (c + 1 < NCH) {
            A_STORE(areg, cur ^ 1, c + 1);
            CP_WAIT0();
        }
        __syncthreads();
    }

    // ---- epilogue: bias + relu + residual + store --------------------------
    #pragma unroll
    for (int mt = 0; mt < 2; mt++) {
        #pragma unroll
        for (int nt = 0; nt < 8; nt++) {
            int nloc = wn * 64 + nt * 8 + (L & 3) * 2;
            int ncol = nh * 128 + nloc;
            float bx = bias[nloc], by = bias[nloc + 1];
            #pragma unroll
            for (int h = 0; h < 2; h++) {
                int n = m0 + wm * 32 + mt * 16 + (L >> 2) + h * 8;
                if (n < N_NODES) {
                    float2 xr = *(const float2*)&x[(size_t)n * D + ncol];
                    float2 r;
                    r.x = fmaxf(acc[mt][nt][h * 2 + 0] + bx, 0.f) + xr.x;
                    r.y = fmaxf(acc[mt][nt][h * 2 + 1] + by, 0.f) + xr.y;
                    *(float2*)&g_h1[(size_t)n * D + ncol] = r;
                }
            }
        }
    }
}

// ---------------- packed f32x2 helpers (for MLP) -----------------------------
typedef unsigned long long u64;
__device__ __forceinline__ u64 f32x2_fma(u64 a, u64 b, u64 c) {
    u64 d;
    asm("fma.rn.f32x2 %0, %1, %2, %3;" : "=l"(d) : "l"(a), "l"(b), "l"(c));
    return d;
}

// ---------------- fused MLP: 256->128->32->1 (f32x2 along K) ----------------
struct MlpSmem {
    float W1s[128][260];
    float W2s[32][132];
    float h1s[32][260];
    float h2s[32][132];
    float h3s[32][36];
    float b1s[128];
    float b2s[32];
    float W3s[32];
    float b3s;
};

__global__ __launch_bounds__(256) void mlp_kernel(
        const float* __restrict__ W1, const float* __restrict__ b1,
        const float* __restrict__ W2, const float* __restrict__ b2,
        const float* __restrict__ W3, const float* __restrict__ b3,
        float* __restrict__ out) {
    extern __shared__ MlpSmem smem_buf[];
    MlpSmem* s = smem_buf;
    int t  = threadIdx.x;
    int n0 = blockIdx.x * 32;

    const float4* W14 = (const float4*)W1;
    for (int f = t; f < 128 * 64; f += 256) {
        int o = f >> 6, k4 = f & 63;
        *(float4*)&s->W1s[o][k4 * 4] = W14[f];
    }
    const float4* W24 = (const float4*)W2;
    for (int f = t; f < 32 * 32; f += 256) {
        int o = f >> 5, k4 = f & 31;
        *(float4*)&s->W2s[o][k4 * 4] = W24[f];
    }
    const float4* h14 = (const float4*)g_h1;
    for (int f = t; f < 32 * 64; f += 256) {
        int node = f >> 6, k4 = f & 63;
        *(float4*)&s->h1s[node][k4 * 4] = h14[(size_t)(n0 + node) * 64 + k4];
    }
    if (t < 128) s->b1s[t] = b1[t];
    if (t < 32) { s->b2s[t] = b2[t]; s->W3s[t] = W3[t]; }
    if (t == 0) s->b3s = b3[0];
    __syncthreads();

    int node = t >> 3;
    int og   = t & 7;

    {   // layer 1: 256 -> 128
        u64 acc[16];
        #pragma unroll
        for (int j = 0; j < 16; j++) acc[j] = 0ull;
        for (int k4 = 0; k4 < 64; k4++) {
            ulonglong2 h = *(const ulonglong2*)&s->h1s[node][k4 * 4];
            #pragma unroll
            for (int j = 0; j < 16; j++) {
                ulonglong2 w = *(const ulonglong2*)&s->W1s[og + 8 * j][k4 * 4];
                acc[j] = f32x2_fma(h.x, w.x, acc[j]);
                acc[j] = f32x2_fma(h.y, w.y, acc[j]);
            }
        }
        #pragma unroll
        for (int j = 0; j < 16; j++) {
            float2 a = *(float2*)&acc[j];
            s->h2s[node][og + 8 * j] = fmaxf(a.x + a.y + s->b1s[og + 8 * j], 0.f);
        }
    }
    __syncthreads();

    {   // layer 2: 128 -> 32
        u64 acc[4];
        #pragma unroll
        for (int j = 0; j < 4; j++) acc[j] = 0ull;
        for (int k4 = 0; k4 < 32; k4++) {
            ulonglong2 h = *(const ulonglong2*)&s->h2s[node][k4 * 4];
            #pragma unroll
            for (int j = 0; j < 4; j++) {
                ulonglong2 w = *(const ulonglong2*)&s->W2s[og + 8 * j][k4 * 4];
                acc[j] = f32x2_fma(h.x, w.x, acc[j]);
                acc[j] = f32x2_fma(h.y, w.y, acc[j]);
            }
        }
        #pragma unroll
        for (int j = 0; j < 4; j++) {
            float2 a = *(float2*)&acc[j];
            s->h3s[node][og + 8 * j] = fmaxf(a.x + a.y + s->b2s[og + 8 * j], 0.f);
        }
    }
    __syncthreads();

    // layer 3: 32 -> 1
    if (t < 32) {
        int n = n0 + t;
        if (n < N_NODES) {
            float v = s->b3s;
            #pragma unroll
            for (int k = 0; k < 32; k++) v += s->h3s[t][k] * s->W3s[k];
            out[n] = v;
        }
    }
}

// ---------------- launch -----------------------------------------------------
extern "C" void kernel_launch(void* const* d_in, const int* in_sizes, int n_in,
                              void* d_out, int out_size) {
    const float*     x  = (const float*)d_in[0];
    const long long* ei = (const long long*)d_in[1];
    const float*     Wl = (const float*)d_in[2];
    const float*     bl = (const float*)d_in[3];
    const float*     Wr = (const float*)d_in[4];
    const float*     W1 = (const float*)d_in[5];
    const float*     b1 = (const float*)d_in[6];
    const float*     W2 = (const float*)d_in[7];
    const float*     b2 = (const float*)d_in[8];
    const float*     W3 = (const float*)d_in[9];
    const float*     b3 = (const float*)d_in[10];
    float* out = (float*)d_out;

    zero_kernel<<<2048, 256>>>();
    detect_kernel<<<1, 32>>>((const int*)ei);
    prep_kernel<<<512, 256>>>(Wl, Wr);
    scatter_kernel<<<(N_EDGES * 8 + 255) / 256, 256>>>((const float4*)x, ei);

    cudaFuncSetAttribute(conv_kernel, cudaFuncAttributeMaxDynamicSharedMemorySize,
                         CONV_SMEM);
    conv_kernel<<<dim3(2, NPAD / 128), 256, CONV_SMEM>>>(x, bl);

    cudaFuncSetAttribute(mlp_kernel, cudaFuncAttributeMaxDynamicSharedMemorySize,
                         (int)sizeof(MlpSmem));
    mlp_kernel<<<NPAD / 32, 256, sizeof(MlpSmem)>>>(W1, b1, W2, b2, W3, b3, out);
}